// round 1
// baseline (speedup 1.0000x reference)
#include <cuda_runtime.h>
#include <cuda_bf16.h>
#include <math.h>

// Problem constants: B=2, L=2048, D=1024, H=16, hd=64
#define Bsz 2
#define Lsz 2048
#define Dsz 1024
#define Hsz 16
#define HDsz 64

// Scratch (device globals: no allocation allowed)
__device__ float g_q[Bsz * Hsz * Lsz * HDsz];   // [b][h][l][d]
__device__ float g_k[Bsz * Hsz * Lsz * HDsz];
__device__ float g_v[Bsz * Hsz * Lsz * HDsz];
__device__ float g_ao[Bsz * Lsz * Dsz];         // attention out, [b][l][h*64+d]

// ---------------------------------------------------------------------------
// 128x128x(K=1024) SGEMM core:  C[m,n] = sum_k A[m,k] * W[n,k]
// A, W passed already offset to the tile's first row. 256 threads, 8x8/thread.
// ---------------------------------------------------------------------------
__device__ __forceinline__ void sgemm_128x128(const float* __restrict__ A,
                                              const float* __restrict__ W,
                                              float acc[8][8]) {
    __shared__ float As[8][132];
    __shared__ float Ws[8][132];

    const int tid = threadIdx.x;
    const int tr = (tid >> 4) << 3;   // 0..120, row of 8x8 tile
    const int tc = (tid & 15) << 3;   // 0..120, col of 8x8 tile
    const int lr = tid >> 1;          // 0..127 row to load
    const int lk = (tid & 1) << 2;    // 0 or 4

    const float* Ap = A + lr * Dsz + lk;
    const float* Wp = W + lr * Dsz + lk;

    float4 a4 = *(const float4*)Ap;
    float4 w4 = *(const float4*)Wp;

#pragma unroll 1
    for (int kt = 0; kt < Dsz / 8; kt++) {
        __syncthreads();
        As[lk + 0][lr] = a4.x; As[lk + 1][lr] = a4.y;
        As[lk + 2][lr] = a4.z; As[lk + 3][lr] = a4.w;
        Ws[lk + 0][lr] = w4.x; Ws[lk + 1][lr] = w4.y;
        Ws[lk + 2][lr] = w4.z; Ws[lk + 3][lr] = w4.w;
        __syncthreads();
        if (kt < Dsz / 8 - 1) {
            a4 = *(const float4*)(Ap + (kt + 1) * 8);
            w4 = *(const float4*)(Wp + (kt + 1) * 8);
        }
#pragma unroll
        for (int k = 0; k < 8; k++) {
            float ar[8], wr[8];
            *(float4*)&ar[0] = *(const float4*)&As[k][tr];
            *(float4*)&ar[4] = *(const float4*)&As[k][tr + 4];
            *(float4*)&wr[0] = *(const float4*)&Ws[k][tc];
            *(float4*)&wr[4] = *(const float4*)&Ws[k][tc + 4];
#pragma unroll
            for (int i = 0; i < 8; i++)
#pragma unroll
                for (int j = 0; j < 8; j++)
                    acc[i][j] = fmaf(ar[i], wr[j], acc[i][j]);
        }
    }
}

// ---------------------------------------------------------------------------
// QKV projection: grid (N/128=8, M/128=32, 3). Writes into [b][h][l][d].
// ---------------------------------------------------------------------------
__global__ void __launch_bounds__(256) qkv_kernel(const float* __restrict__ x,
                                                  const float* __restrict__ wq,
                                                  const float* __restrict__ wk,
                                                  const float* __restrict__ wv) {
    const float* W = (blockIdx.z == 0) ? wq : (blockIdx.z == 1) ? wk : wv;
    float* dst = (blockIdx.z == 0) ? g_q : (blockIdx.z == 1) ? g_k : g_v;

    const int rowBase = blockIdx.y * 128;
    const int colBase = blockIdx.x * 128;

    float acc[8][8];
#pragma unroll
    for (int i = 0; i < 8; i++)
#pragma unroll
        for (int j = 0; j < 8; j++) acc[i][j] = 0.f;

    sgemm_128x128(x + (size_t)rowBase * Dsz, W + (size_t)colBase * Dsz, acc);

    const int tid = threadIdx.x;
    const int tr = (tid >> 4) << 3;
    const int tc = (tid & 15) << 3;
    const int n0 = colBase + tc;
    const int h = n0 >> 6;
    const int dd = n0 & 63;
#pragma unroll
    for (int i = 0; i < 8; i++) {
        int m = rowBase + tr + i;
        int b = m >> 11, l = m & 2047;
        float* o = dst + (((size_t)(b * Hsz + h) * Lsz + l) * HDsz + dd);
        *(float4*)(o)     = make_float4(acc[i][0], acc[i][1], acc[i][2], acc[i][3]);
        *(float4*)(o + 4) = make_float4(acc[i][4], acc[i][5], acc[i][6], acc[i][7]);
    }
}

// ---------------------------------------------------------------------------
// Output projection: C = g_ao @ wo^T  ->  d_out
// ---------------------------------------------------------------------------
__global__ void __launch_bounds__(256) oproj_kernel(const float* __restrict__ wo,
                                                    float* __restrict__ out) {
    const int rowBase = blockIdx.y * 128;
    const int colBase = blockIdx.x * 128;

    float acc[8][8];
#pragma unroll
    for (int i = 0; i < 8; i++)
#pragma unroll
        for (int j = 0; j < 8; j++) acc[i][j] = 0.f;

    sgemm_128x128(g_ao + (size_t)rowBase * Dsz, wo + (size_t)colBase * Dsz, acc);

    const int tid = threadIdx.x;
    const int tr = (tid >> 4) << 3;
    const int tc = (tid & 15) << 3;
#pragma unroll
    for (int i = 0; i < 8; i++) {
        float* o = out + (size_t)(rowBase + tr + i) * Dsz + colBase + tc;
        *(float4*)(o)     = make_float4(acc[i][0], acc[i][1], acc[i][2], acc[i][3]);
        *(float4*)(o + 4) = make_float4(acc[i][4], acc[i][5], acc[i][6], acc[i][7]);
    }
}

// ---------------------------------------------------------------------------
// RoPE in-place on g_q and g_k. Each thread handles pair (d, d+32) of one row.
// rope(x)[d]      = x[d]*cos[d]      - x[d+32]*sin[d]        (d < 32)
// rope(x)[d+32]   = x[d+32]*cos[d+32] + x[d]*sin[d+32]
// ---------------------------------------------------------------------------
__global__ void rope_kernel(const float* __restrict__ cosp,
                            const float* __restrict__ sinp) {
    const int idx = blockIdx.x * blockDim.x + threadIdx.x;  // B*H*L*32 threads
    const int row = idx >> 5;         // 0 .. B*H*L-1
    const int d = idx & 31;
    const int l = row & (Lsz - 1);

    const float c1 = cosp[l * HDsz + d];
    const float s1 = sinp[l * HDsz + d];
    const float c2 = cosp[l * HDsz + d + 32];
    const float s2 = sinp[l * HDsz + d + 32];

    const size_t base = (size_t)row * HDsz;

    float x1 = g_q[base + d];
    float x2 = g_q[base + d + 32];
    g_q[base + d]      = x1 * c1 - x2 * s1;
    g_q[base + d + 32] = x2 * c2 + x1 * s2;

    x1 = g_k[base + d];
    x2 = g_k[base + d + 32];
    g_k[base + d]      = x1 * c1 - x2 * s1;
    g_k[base + d + 32] = x2 * c2 + x1 * s2;
}

// ---------------------------------------------------------------------------
// Causal flash attention.  Q-tile 128 rows, KV-tile 64. 256 threads.
// Thread grid for both GEMMs: ty = tid/8 (4 rows each), tx = tid%8 (8 cols).
// smem (dynamic, floats):
//   Qst[64][132]  d-major Q (pre-scaled by 1/8)
//   Kst[64][68]   d-major K
//   Vs [64][68]   j-major V
//   Pst[64][132]  j-major P
// ---------------------------------------------------------------------------
#define QP 132
#define KP 68
#define FLASH_SMEM_FLOATS (64 * QP + 64 * KP + 64 * KP + 64 * QP)

__global__ void __launch_bounds__(256, 2) flash_kernel() {
    extern __shared__ float sm[];
    float* Qst = sm;                    // 64*132
    float* Kst = Qst + 64 * QP;         // 64*68
    float* Vs  = Kst + 64 * KP;         // 64*68
    float* Pst = Vs  + 64 * KP;         // 64*132

    const int tid = threadIdx.x;
    const int bh = blockIdx.y;              // 0..31
    const int qt = blockIdx.x;              // 0..15
    const int q0 = qt * 128;
    const size_t bhBase = (size_t)bh * Lsz * HDsz;

    // ---- Load Q tile transposed, scaled by 1/sqrt(hd)=0.125 ----
    {
        const int lr = tid >> 1;            // 0..127
        const int db = (tid & 1) * 32;
        const float* qrow = g_q + bhBase + (size_t)(q0 + lr) * HDsz + db;
#pragma unroll
        for (int t = 0; t < 8; t++) {
            float4 v = *(const float4*)(qrow + t * 4);
            int d = db + t * 4;
            Qst[(d + 0) * QP + lr] = v.x * 0.125f;
            Qst[(d + 1) * QP + lr] = v.y * 0.125f;
            Qst[(d + 2) * QP + lr] = v.z * 0.125f;
            Qst[(d + 3) * QP + lr] = v.w * 0.125f;
        }
    }

    const int ty = tid >> 3;      // 0..31
    const int tx = tid & 7;       // 0..7
    const int r0 = ty * 4;        // rows (4)
    const int c0 = tx * 8;        // cols (8)

    float accO[4][8];
#pragma unroll
    for (int i = 0; i < 4; i++)
#pragma unroll
        for (int j = 0; j < 8; j++) accO[i][j] = 0.f;
    float m_run[4] = {-1e30f, -1e30f, -1e30f, -1e30f};
    float l_run[4] = {0.f, 0.f, 0.f, 0.f};

    const int nkt = 2 * qt + 2;   // causal: kv tiles 0..nkt-1
    for (int kt = 0; kt < nkt; kt++) {
        const int j0 = kt * 64;
        __syncthreads();   // previous iteration done with Kst/Vs/Pst

        // ---- Load K (transposed) and V (direct) ----
        {
            const int jr = tid >> 2;          // 0..63
            const int db = (tid & 3) * 16;
            const float* krow = g_k + bhBase + (size_t)(j0 + jr) * HDsz + db;
            const float* vrow = g_v + bhBase + (size_t)(j0 + jr) * HDsz + db;
#pragma unroll
            for (int t = 0; t < 4; t++) {
                float4 v = *(const float4*)(krow + t * 4);
                int d = db + t * 4;
                Kst[(d + 0) * KP + jr] = v.x;
                Kst[(d + 1) * KP + jr] = v.y;
                Kst[(d + 2) * KP + jr] = v.z;
                Kst[(d + 3) * KP + jr] = v.w;
                *(float4*)(Vs + jr * KP + db + t * 4) = *(const float4*)(vrow + t * 4);
            }
        }
        __syncthreads();

        // ---- GEMM1: S = Qs * Ks^T ----
        float S[4][8];
#pragma unroll
        for (int i = 0; i < 4; i++)
#pragma unroll
            for (int j = 0; j < 8; j++) S[i][j] = 0.f;

#pragma unroll 8
        for (int d = 0; d < 64; d++) {
            float4 q4 = *(const float4*)(Qst + d * QP + r0);
            float4 ka = *(const float4*)(Kst + d * KP + c0);
            float4 kb = *(const float4*)(Kst + d * KP + c0 + 4);
            float qv[4] = {q4.x, q4.y, q4.z, q4.w};
            float kv[8] = {ka.x, ka.y, ka.z, ka.w, kb.x, kb.y, kb.z, kb.w};
#pragma unroll
            for (int i = 0; i < 4; i++)
#pragma unroll
                for (int j = 0; j < 8; j++)
                    S[i][j] = fmaf(qv[i], kv[j], S[i][j]);
        }

        // ---- causal mask (only the 2 diagonal tiles need it) ----
        if (kt >= 2 * qt) {
#pragma unroll
            for (int i = 0; i < 4; i++) {
                int r = q0 + r0 + i;
#pragma unroll
                for (int j = 0; j < 8; j++) {
                    if (j0 + c0 + j > r) S[i][j] = -1e30f;
                }
            }
        }

        // ---- online softmax (rows spread over 8 tx lanes) ----
#pragma unroll
        for (int i = 0; i < 4; i++) {
            float mloc = S[i][0];
#pragma unroll
            for (int j = 1; j < 8; j++) mloc = fmaxf(mloc, S[i][j]);
            mloc = fmaxf(mloc, __shfl_xor_sync(0xffffffffu, mloc, 1));
            mloc = fmaxf(mloc, __shfl_xor_sync(0xffffffffu, mloc, 2));
            mloc = fmaxf(mloc, __shfl_xor_sync(0xffffffffu, mloc, 4));
            float mnew = fmaxf(m_run[i], mloc);
            float scale = __expf(m_run[i] - mnew);
            float ls = 0.f;
#pragma unroll
            for (int j = 0; j < 8; j++) {
                float p = __expf(S[i][j] - mnew);
                S[i][j] = p;
                ls += p;
            }
            ls += __shfl_xor_sync(0xffffffffu, ls, 1);
            ls += __shfl_xor_sync(0xffffffffu, ls, 2);
            ls += __shfl_xor_sync(0xffffffffu, ls, 4);
            l_run[i] = l_run[i] * scale + ls;
            m_run[i] = mnew;
#pragma unroll
            for (int j = 0; j < 8; j++) accO[i][j] *= scale;
            // stash P transposed for GEMM2
#pragma unroll
            for (int j = 0; j < 8; j++)
                Pst[(c0 + j) * QP + r0 + i] = S[i][j];
        }
        __syncthreads();

        // ---- GEMM2: O += P * V ----
#pragma unroll 8
        for (int j = 0; j < 64; j++) {
            float4 p4 = *(const float4*)(Pst + j * QP + r0);
            float4 va = *(const float4*)(Vs + j * KP + c0);
            float4 vb = *(const float4*)(Vs + j * KP + c0 + 4);
            float pv[4] = {p4.x, p4.y, p4.z, p4.w};
            float vv[8] = {va.x, va.y, va.z, va.w, vb.x, vb.y, vb.z, vb.w};
#pragma unroll
            for (int i = 0; i < 4; i++)
#pragma unroll
                for (int jj = 0; jj < 8; jj++)
                    accO[i][jj] = fmaf(pv[i], vv[jj], accO[i][jj]);
        }
    }

    // ---- epilogue: normalize & write to g_ao [b][l][h*64+d] ----
    const int b = bh >> 4;
    const int h = bh & 15;
#pragma unroll
    for (int i = 0; i < 4; i++) {
        float inv = 1.f / l_run[i];
        int row = q0 + r0 + i;
        float* o = g_ao + ((size_t)b * Lsz + row) * Dsz + h * HDsz + c0;
        *(float4*)(o)     = make_float4(accO[i][0] * inv, accO[i][1] * inv,
                                        accO[i][2] * inv, accO[i][3] * inv);
        *(float4*)(o + 4) = make_float4(accO[i][4] * inv, accO[i][5] * inv,
                                        accO[i][6] * inv, accO[i][7] * inv);
    }
}

// ---------------------------------------------------------------------------
extern "C" void kernel_launch(void* const* d_in, const int* in_sizes, int n_in,
                              void* d_out, int out_size) {
    (void)in_sizes; (void)n_in; (void)out_size;
    const float* x    = (const float*)d_in[0];
    const float* cosp = (const float*)d_in[1];
    const float* sinp = (const float*)d_in[2];
    const float* wq   = (const float*)d_in[3];
    const float* wk   = (const float*)d_in[4];
    const float* wv   = (const float*)d_in[5];
    const float* wo   = (const float*)d_in[6];
    float* out = (float*)d_out;

    // 1) QKV projections into [B,H,L,hd]
    qkv_kernel<<<dim3(Dsz / 128, (Bsz * Lsz) / 128, 3), 256>>>(x, wq, wk, wv);

    // 2) RoPE on q, k (in place)
    {
        int threads = Bsz * Hsz * Lsz * 32;
        rope_kernel<<<threads / 256, 256>>>(cosp, sinp);
    }

    // 3) causal flash attention -> g_ao [B,L,D]
    {
        size_t smem = FLASH_SMEM_FLOATS * sizeof(float);
        cudaFuncSetAttribute(flash_kernel,
                             cudaFuncAttributeMaxDynamicSharedMemorySize,
                             (int)smem);
        flash_kernel<<<dim3(Lsz / 128, Bsz * Hsz), 256, smem>>>();
    }

    // 4) output projection -> d_out
    oproj_kernel<<<dim3(Dsz / 128, (Bsz * Lsz) / 128), 256>>>(wo, out);
}

// round 3
// speedup vs baseline: 1.4584x; 1.4584x over previous
#include <cuda_runtime.h>
#include <cuda_bf16.h>
#include <math.h>
#include <stdint.h>

// Problem constants: B=2, L=2048, D=1024, H=16, hd=64
#define Bsz 2
#define Lsz 2048
#define Dsz 1024
#define Hsz 16
#define HDsz 64

// ---------------- device scratch (no allocation allowed) -------------------
__device__ float g_q[Bsz * Hsz * Lsz * HDsz];       // [b][h][l][d]
__device__ float g_k[Bsz * Hsz * Lsz * HDsz];
__device__ float g_v[Bsz * Hsz * Lsz * HDsz];
__device__ float g_ao[Bsz * Lsz * Dsz];             // attention out [b][l][h*64+d]
__device__ float g_x2[2 * Bsz * Lsz * Dsz];         // x split, interleaved hi/lo
__device__ float g_w2[4 * 2 * Dsz * Dsz];           // wq,wk,wv,wo split
__device__ float g_ao2[2 * Bsz * Lsz * Dsz];        // g_ao split

// ---------------- helpers --------------------------------------------------
__device__ __forceinline__ uint32_t fu(float x) { return __float_as_uint(x); }
__device__ __forceinline__ float uf(uint32_t x) { return __uint_as_float(x); }

// split fp32 -> (tf32 hi, tf32 lo), x ~= hi + lo with ~2^-22 rel error
__device__ __forceinline__ void split2(float x, uint32_t& h, uint32_t& l) {
    uint32_t hb;
    asm("cvt.rna.tf32.f32 %0, %1;" : "=r"(hb) : "f"(x));
    float r = x - uf(hb);
    uint32_t lb;
    asm("cvt.rna.tf32.f32 %0, %1;" : "=r"(lb) : "f"(r));
    h = hb; l = lb;
}

__device__ __forceinline__ void mma8(float c[4], const uint32_t a[4], const uint32_t b[2]) {
    asm volatile(
        "mma.sync.aligned.m16n8k8.row.col.f32.tf32.tf32.f32 "
        "{%0,%1,%2,%3}, {%4,%5,%6,%7}, {%8,%9}, {%0,%1,%2,%3};\n"
        : "+f"(c[0]), "+f"(c[1]), "+f"(c[2]), "+f"(c[3])
        : "r"(a[0]), "r"(a[1]), "r"(a[2]), "r"(a[3]), "r"(b[0]), "r"(b[1]));
}

// ---------------- split kernel: fp32 array -> interleaved hi/lo ------------
__global__ void split_kernel(const float* __restrict__ in,
                             float* __restrict__ out2, int n) {
    int i = blockIdx.x * blockDim.x + threadIdx.x;
    if (i < n) {
        uint32_t h, l;
        split2(in[i], h, l);
        *(float2*)(out2 + 2 * (size_t)i) = make_float2(uf(h), uf(l));
    }
}

// splits all four weight matrices in one launch: in-order wq,wk,wv,wo
__global__ void split_w_kernel(const float* __restrict__ wq,
                               const float* __restrict__ wk,
                               const float* __restrict__ wv,
                               const float* __restrict__ wo,
                               float* __restrict__ out2) {
    const int nw = Dsz * Dsz;
    int i = blockIdx.x * blockDim.x + threadIdx.x;   // 0 .. 4*nw-1
    int m = i >> 20;                                  // which matrix (nw = 2^20)
    int r = i & (nw - 1);
    const float* src = (m == 0) ? wq : (m == 1) ? wk : (m == 2) ? wv : wo;
    uint32_t h, l;
    split2(src[r], h, l);
    *(float2*)(out2 + (size_t)m * 2 * nw + 2 * (size_t)r) = make_float2(uf(h), uf(l));
}

// ---------------- TF32 split GEMM core -------------------------------------
// C[128,128] tile of  C = A @ W^T ,  A2/W2 are hi/lo-interleaved rows (2K floats).
// BK=16 (32 interleaved floats), 2-stage cp.async pipeline, 256 thr, 8 warps 2x4.
#define GSTR 40                         // 32 data + 8 pad floats per smem row
#define GEMM_SMEM (2 * 2 * 128 * GSTR * 4)   // 81920 B

__device__ __forceinline__ void gemm128_tf32(const float* __restrict__ A2,
                                             const float* __restrict__ W2,
                                             int rowBase, int colBase,
                                             float C[4][4][4], float* sm) {
    const int tid = threadIdx.x;
    const int wid = tid >> 5, lane = tid & 31;
    const int g = lane >> 2, t = lane & 3;
    const int wm = (wid >> 2) * 64, wn = (wid & 3) * 32;

    auto load_tile = [&](int kt, int s) {
        float* As = sm + s * (2 * 128 * GSTR);
        float* Ws = As + 128 * GSTR;
#pragma unroll
        for (int i = 0; i < 4; i++) {
            int idx4 = tid + 256 * i;
            int row = idx4 >> 3;
            int c4 = (idx4 & 7) * 4;
            const float* ga = A2 + (size_t)(rowBase + row) * (2 * Dsz) + kt * 32 + c4;
            const float* gw = W2 + (size_t)(colBase + row) * (2 * Dsz) + kt * 32 + c4;
            uint32_t sa = (uint32_t)__cvta_generic_to_shared(As + row * GSTR + c4);
            uint32_t sw = (uint32_t)__cvta_generic_to_shared(Ws + row * GSTR + c4);
            asm volatile("cp.async.cg.shared.global [%0],[%1],16;\n" ::"r"(sa), "l"(ga) : "memory");
            asm volatile("cp.async.cg.shared.global [%0],[%1],16;\n" ::"r"(sw), "l"(gw) : "memory");
        }
    };

    load_tile(0, 0);
    asm volatile("cp.async.commit_group;\n" ::: "memory");

    for (int kt = 0; kt < Dsz / 16; kt++) {
        asm volatile("cp.async.wait_group 0;\n" ::: "memory");
        __syncthreads();
        if (kt + 1 < Dsz / 16) {
            load_tile(kt + 1, (kt + 1) & 1);
            asm volatile("cp.async.commit_group;\n" ::: "memory");
        }
        const float* As = sm + (kt & 1) * (2 * 128 * GSTR);
        const float* Ws = As + 128 * GSTR;
#pragma unroll
        for (int ks = 0; ks < 2; ks++) {
            const int ak = ks * 8 + t;
            uint32_t bh[4][2], bl[4][2];
#pragma unroll
            for (int nt = 0; nt < 4; nt++) {
                int br = wn + nt * 8 + g;
                float2 b0 = *(const float2*)(Ws + br * GSTR + 2 * ak);
                float2 b1 = *(const float2*)(Ws + br * GSTR + 2 * ak + 8);
                bh[nt][0] = fu(b0.x); bl[nt][0] = fu(b0.y);
                bh[nt][1] = fu(b1.x); bl[nt][1] = fu(b1.y);
            }
#pragma unroll
            for (int mt = 0; mt < 4; mt++) {
                int ar = wm + mt * 16 + g;
                uint32_t ah[4], al[4];
                float2 a0 = *(const float2*)(As + ar * GSTR + 2 * ak);
                float2 a1 = *(const float2*)(As + (ar + 8) * GSTR + 2 * ak);
                float2 a2 = *(const float2*)(As + ar * GSTR + 2 * ak + 8);
                float2 a3 = *(const float2*)(As + (ar + 8) * GSTR + 2 * ak + 8);
                ah[0] = fu(a0.x); al[0] = fu(a0.y);
                ah[1] = fu(a1.x); al[1] = fu(a1.y);
                ah[2] = fu(a2.x); al[2] = fu(a2.y);
                ah[3] = fu(a3.x); al[3] = fu(a3.y);
#pragma unroll
                for (int nt = 0; nt < 4; nt++) {
                    mma8(C[mt][nt], ah, bh[nt]);
                    mma8(C[mt][nt], al, bh[nt]);
                    mma8(C[mt][nt], ah, bl[nt]);
                }
            }
        }
    }
}

// ---------------- QKV projection -------------------------------------------
__global__ void __launch_bounds__(256, 2) qkv_tf32_kernel() {
    extern __shared__ float sm[];
    const int z = blockIdx.z;
    const float* W2 = g_w2 + (size_t)z * (2 * Dsz * Dsz);
    float* dst = (z == 0) ? g_q : (z == 1) ? g_k : g_v;
    const int rowBase = blockIdx.y * 128;
    const int colBase = blockIdx.x * 128;

    float C[4][4][4];
#pragma unroll
    for (int a = 0; a < 4; a++)
#pragma unroll
        for (int b = 0; b < 4; b++)
#pragma unroll
            for (int c = 0; c < 4; c++) C[a][b][c] = 0.f;

    gemm128_tf32(g_x2, W2, rowBase, colBase, C, sm);

    const int tid = threadIdx.x;
    const int wid = tid >> 5, lane = tid & 31;
    const int g = lane >> 2, t = lane & 3;
    const int wm = (wid >> 2) * 64, wn = (wid & 3) * 32;
#pragma unroll
    for (int mt = 0; mt < 4; mt++) {
#pragma unroll
        for (int nt = 0; nt < 4; nt++) {
            int r = rowBase + wm + mt * 16 + g;
            int n = colBase + wn + nt * 8 + 2 * t;
            int h = n >> 6, d = n & 63;
            int b = r >> 11, l = r & 2047;
            float* p0 = dst + (((size_t)(b * Hsz + h) * Lsz + l) * HDsz + d);
            float* p1 = dst + (((size_t)(b * Hsz + h) * Lsz + (l + 8)) * HDsz + d);
            *(float2*)p0 = make_float2(C[mt][nt][0], C[mt][nt][1]);
            *(float2*)p1 = make_float2(C[mt][nt][2], C[mt][nt][3]);
        }
    }
}

// ---------------- Output projection ----------------------------------------
__global__ void __launch_bounds__(256, 2) oproj_tf32_kernel(float* __restrict__ out) {
    extern __shared__ float sm[];
    const int rowBase = blockIdx.y * 128;
    const int colBase = blockIdx.x * 128;

    float C[4][4][4];
#pragma unroll
    for (int a = 0; a < 4; a++)
#pragma unroll
        for (int b = 0; b < 4; b++)
#pragma unroll
            for (int c = 0; c < 4; c++) C[a][b][c] = 0.f;

    gemm128_tf32(g_ao2, g_w2 + (size_t)3 * (2 * Dsz * Dsz), rowBase, colBase, C, sm);

    const int tid = threadIdx.x;
    const int wid = tid >> 5, lane = tid & 31;
    const int g = lane >> 2, t = lane & 3;
    const int wm = (wid >> 2) * 64, wn = (wid & 3) * 32;
#pragma unroll
    for (int mt = 0; mt < 4; mt++) {
#pragma unroll
        for (int nt = 0; nt < 4; nt++) {
            int r = rowBase + wm + mt * 16 + g;
            int n = colBase + wn + nt * 8 + 2 * t;
            *(float2*)(out + (size_t)r * Dsz + n) = make_float2(C[mt][nt][0], C[mt][nt][1]);
            *(float2*)(out + (size_t)(r + 8) * Dsz + n) = make_float2(C[mt][nt][2], C[mt][nt][3]);
        }
    }
}

// ---------------- RoPE in-place on g_q, g_k --------------------------------
__global__ void rope_kernel(const float* __restrict__ cosp,
                            const float* __restrict__ sinp) {
    const int idx = blockIdx.x * blockDim.x + threadIdx.x;
    const int row = idx >> 5;
    const int d = idx & 31;
    const int l = row & (Lsz - 1);

    const float c1 = cosp[l * HDsz + d];
    const float s1 = sinp[l * HDsz + d];
    const float c2 = cosp[l * HDsz + d + 32];
    const float s2 = sinp[l * HDsz + d + 32];

    const size_t base = (size_t)row * HDsz;

    float x1 = g_q[base + d];
    float x2 = g_q[base + d + 32];
    g_q[base + d]      = x1 * c1 - x2 * s1;
    g_q[base + d + 32] = x2 * c2 + x1 * s2;

    x1 = g_k[base + d];
    x2 = g_k[base + d + 32];
    g_k[base + d]      = x1 * c1 - x2 * s1;
    g_k[base + d + 32] = x2 * c2 + x1 * s2;
}

// ---------------- Flash attention (split-TF32 mma) -------------------------
// Q tile 128 x kv tile 64, 256 threads = 8 warps, warp owns 16 q-rows.
// smem rows hold hi/lo interleaved (128 data floats) + pad -> stride 136.
#define FSTR 136
#define FLASH_SMEM ((128 + 64 + 64 + 128) * FSTR * 4)   // 208896 B

__global__ void __launch_bounds__(256, 1) flashmma_kernel() {
    extern __shared__ float sm[];
    float* Qs = sm;                    // 128 rows
    float* Ks = Qs + 128 * FSTR;       // 64 rows
    float* Vs = Ks + 64 * FSTR;        // 64 rows
    float* Ps = Vs + 64 * FSTR;        // 128 rows

    const int tid = threadIdx.x;
    const int wid = tid >> 5, lane = tid & 31;
    const int g = lane >> 2, t = lane & 3;
    const int bh = blockIdx.y;
    const int qt = gridDim.x - 1 - blockIdx.x;   // big tiles first
    const int q0 = qt * 128;
    const size_t base = (size_t)bh * Lsz * HDsz;

    // ---- load Q (scaled by 1/8) split into smem ----
#pragma unroll
    for (int i = 0; i < 8; i++) {
        int idx4 = tid + 256 * i;
        int row = idx4 >> 4;
        int c4 = (idx4 & 15) * 4;
        float4 v = *(const float4*)(g_q + base + (size_t)(q0 + row) * HDsz + c4);
        uint32_t h0, l0, h1, l1, h2, l2, h3, l3;
        split2(v.x * 0.125f, h0, l0);
        split2(v.y * 0.125f, h1, l1);
        split2(v.z * 0.125f, h2, l2);
        split2(v.w * 0.125f, h3, l3);
        *(float4*)(Qs + row * FSTR + 2 * c4)     = make_float4(uf(h0), uf(l0), uf(h1), uf(l1));
        *(float4*)(Qs + row * FSTR + 2 * c4 + 4) = make_float4(uf(h2), uf(l2), uf(h3), uf(l3));
    }

    float O[8][4];
#pragma unroll
    for (int i = 0; i < 8; i++)
#pragma unroll
        for (int j = 0; j < 4; j++) O[i][j] = 0.f;
    float mr[2] = {-1e30f, -1e30f};
    float lr[2] = {0.f, 0.f};

    const int pr = wid * 16 + g;
    const int nkt = 2 * qt + 2;

    for (int kt = 0; kt < nkt; kt++) {
        const int j0 = kt * 64;
        __syncthreads();   // prev iter done with Ks/Vs (and Q load visible on kt=0)

        // ---- load K, V split ----
#pragma unroll
        for (int i = 0; i < 4; i++) {
            int idx4 = tid + 256 * i;
            int row = idx4 >> 4;
            int c4 = (idx4 & 15) * 4;
            float4 kv4 = *(const float4*)(g_k + base + (size_t)(j0 + row) * HDsz + c4);
            float4 vv4 = *(const float4*)(g_v + base + (size_t)(j0 + row) * HDsz + c4);
            uint32_t h0, l0, h1, l1, h2, l2, h3, l3;
            split2(kv4.x, h0, l0); split2(kv4.y, h1, l1);
            split2(kv4.z, h2, l2); split2(kv4.w, h3, l3);
            *(float4*)(Ks + row * FSTR + 2 * c4)     = make_float4(uf(h0), uf(l0), uf(h1), uf(l1));
            *(float4*)(Ks + row * FSTR + 2 * c4 + 4) = make_float4(uf(h2), uf(l2), uf(h3), uf(l3));
            split2(vv4.x, h0, l0); split2(vv4.y, h1, l1);
            split2(vv4.z, h2, l2); split2(vv4.w, h3, l3);
            *(float4*)(Vs + row * FSTR + 2 * c4)     = make_float4(uf(h0), uf(l0), uf(h1), uf(l1));
            *(float4*)(Vs + row * FSTR + 2 * c4 + 4) = make_float4(uf(h2), uf(l2), uf(h3), uf(l3));
        }
        __syncthreads();

        // ---- GEMM1: S = Qs @ Ks^T ----
        float S[8][4];
#pragma unroll
        for (int i = 0; i < 8; i++)
#pragma unroll
            for (int j = 0; j < 4; j++) S[i][j] = 0.f;

#pragma unroll
        for (int ks = 0; ks < 8; ks++) {
            const int ak = ks * 8 + t;
            uint32_t ah[4], al[4];
            float2 a0 = *(const float2*)(Qs + pr * FSTR + 2 * ak);
            float2 a1 = *(const float2*)(Qs + (pr + 8) * FSTR + 2 * ak);
            float2 a2 = *(const float2*)(Qs + pr * FSTR + 2 * ak + 8);
            float2 a3 = *(const float2*)(Qs + (pr + 8) * FSTR + 2 * ak + 8);
            ah[0] = fu(a0.x); al[0] = fu(a0.y);
            ah[1] = fu(a1.x); al[1] = fu(a1.y);
            ah[2] = fu(a2.x); al[2] = fu(a2.y);
            ah[3] = fu(a3.x); al[3] = fu(a3.y);
#pragma unroll
            for (int nt = 0; nt < 8; nt++) {
                int br = nt * 8 + g;
                float2 b0 = *(const float2*)(Ks + br * FSTR + 2 * ak);
                float2 b1 = *(const float2*)(Ks + br * FSTR + 2 * ak + 8);
                uint32_t bhx[2] = {fu(b0.x), fu(b1.x)};
                uint32_t blx[2] = {fu(b0.y), fu(b1.y)};
                mma8(S[nt], ah, bhx);
                mma8(S[nt], al, bhx);
                mma8(S[nt], ah, blx);
            }
        }

        // ---- causal mask (diagonal tiles only) ----
        if (kt >= 2 * qt) {
            int r0g = q0 + pr;
#pragma unroll
            for (int nt = 0; nt < 8; nt++) {
                int c0 = j0 + nt * 8 + 2 * t;
                if (c0 > r0g)     S[nt][0] = -1e30f;
                if (c0 + 1 > r0g) S[nt][1] = -1e30f;
                if (c0 > r0g + 8)     S[nt][2] = -1e30f;
                if (c0 + 1 > r0g + 8) S[nt][3] = -1e30f;
            }
        }

        // ---- online softmax ----
#pragma unroll
        for (int h2 = 0; h2 < 2; h2++) {
            float mloc = -1e30f;
#pragma unroll
            for (int nt = 0; nt < 8; nt++)
                mloc = fmaxf(mloc, fmaxf(S[nt][2 * h2], S[nt][2 * h2 + 1]));
            mloc = fmaxf(mloc, __shfl_xor_sync(0xffffffffu, mloc, 1));
            mloc = fmaxf(mloc, __shfl_xor_sync(0xffffffffu, mloc, 2));
            float mnew = fmaxf(mr[h2], mloc);
            float sc = __expf(mr[h2] - mnew);
            float ls = 0.f;
#pragma unroll
            for (int nt = 0; nt < 8; nt++) {
                float p0 = __expf(S[nt][2 * h2] - mnew);
                float p1 = __expf(S[nt][2 * h2 + 1] - mnew);
                S[nt][2 * h2] = p0; S[nt][2 * h2 + 1] = p1;
                ls += p0 + p1;
            }
            ls += __shfl_xor_sync(0xffffffffu, ls, 1);
            ls += __shfl_xor_sync(0xffffffffu, ls, 2);
            lr[h2] = lr[h2] * sc + ls;
            mr[h2] = mnew;
#pragma unroll
            for (int nt = 0; nt < 8; nt++) {
                O[nt][2 * h2] *= sc;
                O[nt][2 * h2 + 1] *= sc;
            }
        }

        // ---- store P split (warp-local rows) ----
#pragma unroll
        for (int nt = 0; nt < 8; nt++) {
            int c = nt * 8 + 2 * t;
            uint32_t h0, l0, h1, l1;
            split2(S[nt][0], h0, l0);
            split2(S[nt][1], h1, l1);
            *(float4*)(Ps + pr * FSTR + 2 * c) = make_float4(uf(h0), uf(l0), uf(h1), uf(l1));
            split2(S[nt][2], h0, l0);
            split2(S[nt][3], h1, l1);
            *(float4*)(Ps + (pr + 8) * FSTR + 2 * c) = make_float4(uf(h0), uf(l0), uf(h1), uf(l1));
        }
        __syncwarp();

        // ---- GEMM2: O += P @ V ----
#pragma unroll
        for (int js = 0; js < 8; js++) {
            const int jk = js * 8 + t;
            uint32_t ah[4], al[4];
            float2 a0 = *(const float2*)(Ps + pr * FSTR + 2 * jk);
            float2 a1 = *(const float2*)(Ps + (pr + 8) * FSTR + 2 * jk);
            float2 a2 = *(const float2*)(Ps + pr * FSTR + 2 * jk + 8);
            float2 a3 = *(const float2*)(Ps + (pr + 8) * FSTR + 2 * jk + 8);
            ah[0] = fu(a0.x); al[0] = fu(a0.y);
            ah[1] = fu(a1.x); al[1] = fu(a1.y);
            ah[2] = fu(a2.x); al[2] = fu(a2.y);
            ah[3] = fu(a3.x); al[3] = fu(a3.y);
#pragma unroll
            for (int dt = 0; dt < 8; dt++) {
                float2 b0 = *(const float2*)(Vs + jk * FSTR + 2 * (dt * 8 + g));
                float2 b1 = *(const float2*)(Vs + (jk + 4) * FSTR + 2 * (dt * 8 + g));
                uint32_t bhx[2] = {fu(b0.x), fu(b1.x)};
                uint32_t blx[2] = {fu(b0.y), fu(b1.y)};
                mma8(O[dt], ah, bhx);
                mma8(O[dt], al, bhx);
                mma8(O[dt], ah, blx);
            }
        }
    }

    // ---- epilogue ----
    const float i0 = 1.f / lr[0];
    const float i1 = 1.f / lr[1];
    const int r = q0 + pr;
    const int b = bh >> 4;
    const int h = bh & 15;
    float* ob = g_ao + (size_t)b * Lsz * Dsz + (size_t)h * HDsz;
#pragma unroll
    for (int dt = 0; dt < 8; dt++) {
        int d = dt * 8 + 2 * t;
        *(float2*)(ob + (size_t)r * Dsz + d) =
            make_float2(O[dt][0] * i0, O[dt][1] * i0);
        *(float2*)(ob + (size_t)(r + 8) * Dsz + d) =
            make_float2(O[dt][2] * i1, O[dt][3] * i1);
    }
}

// ---------------------------------------------------------------------------
extern "C" void kernel_launch(void* const* d_in, const int* in_sizes, int n_in,
                              void* d_out, int out_size) {
    (void)in_sizes; (void)n_in; (void)out_size;
    const float* x    = (const float*)d_in[0];
    const float* cosp = (const float*)d_in[1];
    const float* sinp = (const float*)d_in[2];
    const float* wq   = (const float*)d_in[3];
    const float* wk   = (const float*)d_in[4];
    const float* wv   = (const float*)d_in[5];
    const float* wo   = (const float*)d_in[6];
    float* out = (float*)d_out;

    // idempotent, called every invocation (no static guards allowed)
    cudaFuncSetAttribute(qkv_tf32_kernel,
                         cudaFuncAttributeMaxDynamicSharedMemorySize, GEMM_SMEM);
    cudaFuncSetAttribute(oproj_tf32_kernel,
                         cudaFuncAttributeMaxDynamicSharedMemorySize, GEMM_SMEM);
    cudaFuncSetAttribute(flashmma_kernel,
                         cudaFuncAttributeMaxDynamicSharedMemorySize, FLASH_SMEM);

    float *p_x2, *p_w2, *p_ao, *p_ao2;
    cudaGetSymbolAddress((void**)&p_x2, g_x2);
    cudaGetSymbolAddress((void**)&p_w2, g_w2);
    cudaGetSymbolAddress((void**)&p_ao, g_ao);
    cudaGetSymbolAddress((void**)&p_ao2, g_ao2);

    const int nx = Bsz * Lsz * Dsz;       // 4194304
    const int nw = Dsz * Dsz;             // 1048576

    // 1) split inputs into tf32 hi/lo
    split_kernel<<<nx / 256, 256>>>(x, p_x2, nx);
    split_w_kernel<<<4 * nw / 256, 256>>>(wq, wk, wv, wo, p_w2);

    // 2) QKV projections -> g_q/g_k/g_v [B,H,L,hd]
    qkv_tf32_kernel<<<dim3(Dsz / 128, (Bsz * Lsz) / 128, 3), 256, GEMM_SMEM>>>();

    // 3) RoPE in place
    rope_kernel<<<(Bsz * Hsz * Lsz * 32) / 256, 256>>>(cosp, sinp);

    // 4) causal flash attention -> g_ao
    flashmma_kernel<<<dim3(Lsz / 128, Bsz * Hsz), 256, FLASH_SMEM>>>();

    // 5) split attention output, output projection -> d_out
    split_kernel<<<nx / 256, 256>>>(p_ao, p_ao2, nx);
    oproj_tf32_kernel<<<dim3(Dsz / 128, (Bsz * Lsz) / 128), 256, GEMM_SMEM>>>(out);
}

// round 4
// speedup vs baseline: 2.9492x; 2.0222x over previous
#include <cuda_runtime.h>
#include <cuda_bf16.h>
#include <math.h>
#include <stdint.h>

// Problem constants: B=2, L=2048, D=1024, H=16, hd=64
#define Bsz 2
#define Lsz 2048
#define Dsz 1024
#define Hsz 16
#define HDsz 64

#define NQKV (Bsz * Hsz * Lsz * HDsz)   // 4194304
#define NX   (Bsz * Lsz * Dsz)          // 4194304
#define NW   (Dsz * Dsz)                // 1048576 = 2^20

// ---------------- device scratch: bf16 hi/lo planes ------------------------
__device__ __nv_bfloat16 g_xh[NX],  g_xl[NX];
__device__ __nv_bfloat16 g_wh[4 * NW], g_wl[4 * NW];
__device__ __nv_bfloat16 g_qh[NQKV], g_ql[NQKV];
__device__ __nv_bfloat16 g_kh[NQKV], g_kl[NQKV];
__device__ __nv_bfloat16 g_vh[NQKV], g_vl[NQKV];
__device__ __nv_bfloat16 g_aoh[NX], g_aol[NX];

// ---------------- helpers --------------------------------------------------
__device__ __forceinline__ void sbf(float x, __nv_bfloat16& h, __nv_bfloat16& l) {
    h = __float2bfloat16(x);
    l = __float2bfloat16(x - __bfloat162float(h));
}
__device__ __forceinline__ uint32_t packbf(__nv_bfloat16 a, __nv_bfloat16 b) {
    uint16_t au = *(uint16_t*)&a, bu = *(uint16_t*)&b;
    return (uint32_t)au | ((uint32_t)bu << 16);
}

__device__ __forceinline__ void mma16(float c[4], const uint32_t a[4], const uint32_t b[2]) {
    asm volatile(
        "mma.sync.aligned.m16n8k16.row.col.f32.bf16.bf16.f32 "
        "{%0,%1,%2,%3}, {%4,%5,%6,%7}, {%8,%9}, {%0,%1,%2,%3};\n"
        : "+f"(c[0]), "+f"(c[1]), "+f"(c[2]), "+f"(c[3])
        : "r"(a[0]), "r"(a[1]), "r"(a[2]), "r"(a[3]), "r"(b[0]), "r"(b[1]));
}

__device__ __forceinline__ void ldsm_x2_trans(uint32_t& r0, uint32_t& r1, uint32_t addr) {
    asm volatile("ldmatrix.sync.aligned.m8n8.x2.trans.shared.b16 {%0,%1}, [%2];"
                 : "=r"(r0), "=r"(r1) : "r"(addr));
}

// ---------------- split kernels: fp32 -> bf16 hi/lo planes -----------------
__global__ void split_x_kernel(const float* __restrict__ in) {
    int i = blockIdx.x * blockDim.x + threadIdx.x;   // handles elems 2i, 2i+1
    float2 v = *(const float2*)(in + 2 * (size_t)i);
    __nv_bfloat16 h0, l0, h1, l1;
    sbf(v.x, h0, l0); sbf(v.y, h1, l1);
    ((uint32_t*)g_xh)[i] = packbf(h0, h1);
    ((uint32_t*)g_xl)[i] = packbf(l0, l1);
}

__global__ void split_w_kernel(const float* __restrict__ wq,
                               const float* __restrict__ wk,
                               const float* __restrict__ wv,
                               const float* __restrict__ wo) {
    int i = blockIdx.x * blockDim.x + threadIdx.x;
    size_t e = 2 * (size_t)i;
    int m = (int)(e >> 20);
    int r = (int)(e & (NW - 1));
    const float* src = (m == 0) ? wq : (m == 1) ? wk : (m == 2) ? wv : wo;
    float2 v = *(const float2*)(src + r);
    __nv_bfloat16 h0, l0, h1, l1;
    sbf(v.x, h0, l0); sbf(v.y, h1, l1);
    ((uint32_t*)g_wh)[((size_t)m * NW + r) >> 1] = packbf(h0, h1);
    ((uint32_t*)g_wl)[((size_t)m * NW + r) >> 1] = packbf(l0, l1);
}

// ---------------- bf16x3 GEMM core -----------------------------------------
// 128x128 tile of C = A @ W^T. A/W given as hi/lo bf16 planes, row-major [*][Dsz].
// BK=32, 2-stage cp.async pipeline, 256 threads = 8 warps (2x4), warp tile 64x32.
#define GSTRB 40                                  // 32 data + 8 pad bf16 per row
#define PLANE_ELEMS (128 * GSTRB)                 // 5120
#define STAGE_ELEMS (4 * PLANE_ELEMS)             // 20480
#define GEMM_SMEM (2 * STAGE_ELEMS * 2)           // 81920 bytes

__device__ __forceinline__ void gemm128_bf16(const __nv_bfloat16* __restrict__ Ah_g,
                                             const __nv_bfloat16* __restrict__ Al_g,
                                             const __nv_bfloat16* __restrict__ Wh_g,
                                             const __nv_bfloat16* __restrict__ Wl_g,
                                             int rowBase, int colBase,
                                             float C[4][4][4], __nv_bfloat16* sm) {
    const int tid = threadIdx.x;
    const int wid = tid >> 5, lane = tid & 31;
    const int g = lane >> 2, t = lane & 3;
    const int wm = (wid >> 2) * 64, wn = (wid & 3) * 32;

    const __nv_bfloat16* gp0 = Ah_g + (size_t)rowBase * Dsz;
    const __nv_bfloat16* gp1 = Al_g + (size_t)rowBase * Dsz;
    const __nv_bfloat16* gp2 = Wh_g + (size_t)colBase * Dsz;
    const __nv_bfloat16* gp3 = Wl_g + (size_t)colBase * Dsz;

    auto load_tile = [&](int kt, int s) {
        __nv_bfloat16* st = sm + s * STAGE_ELEMS;
        const __nv_bfloat16* gp[4] = {gp0, gp1, gp2, gp3};
#pragma unroll
        for (int p = 0; p < 4; p++) {
#pragma unroll
            for (int i = 0; i < 2; i++) {
                int idx = tid + 256 * i;
                int row = idx >> 2;
                int c8 = (idx & 3) * 8;
                const __nv_bfloat16* src = gp[p] + (size_t)row * Dsz + kt * 32 + c8;
                uint32_t dst = (uint32_t)__cvta_generic_to_shared(
                    st + p * PLANE_ELEMS + row * GSTRB + c8);
                asm volatile("cp.async.cg.shared.global [%0],[%1],16;\n" ::"r"(dst), "l"(src) : "memory");
            }
        }
    };

    load_tile(0, 0);
    asm volatile("cp.async.commit_group;\n" ::: "memory");

    for (int kt = 0; kt < Dsz / 32; kt++) {
        asm volatile("cp.async.wait_group 0;\n" ::: "memory");
        __syncthreads();
        if (kt + 1 < Dsz / 32) {
            load_tile(kt + 1, (kt + 1) & 1);
            asm volatile("cp.async.commit_group;\n" ::: "memory");
        }
        const __nv_bfloat16* st = sm + (kt & 1) * STAGE_ELEMS;
        const __nv_bfloat16* sAh = st;
        const __nv_bfloat16* sAl = st + PLANE_ELEMS;
        const __nv_bfloat16* sWh = st + 2 * PLANE_ELEMS;
        const __nv_bfloat16* sWl = st + 3 * PLANE_ELEMS;

#pragma unroll
        for (int ks = 0; ks < 2; ks++) {
            const int kb = ks * 16 + 2 * t;
            uint32_t bh[4][2], bl[4][2];
#pragma unroll
            for (int nt = 0; nt < 4; nt++) {
                const __nv_bfloat16* wp = sWh + (wn + nt * 8 + g) * GSTRB + kb;
                const __nv_bfloat16* wq_ = sWl + (wn + nt * 8 + g) * GSTRB + kb;
                bh[nt][0] = *(const uint32_t*)wp;
                bh[nt][1] = *(const uint32_t*)(wp + 8);
                bl[nt][0] = *(const uint32_t*)wq_;
                bl[nt][1] = *(const uint32_t*)(wq_ + 8);
            }
#pragma unroll
            for (int mt = 0; mt < 4; mt++) {
                const int ar = wm + mt * 16 + g;
                const __nv_bfloat16* ap = sAh + ar * GSTRB + kb;
                const __nv_bfloat16* aq = sAl + ar * GSTRB + kb;
                uint32_t ah[4], al[4];
                ah[0] = *(const uint32_t*)ap;
                ah[1] = *(const uint32_t*)(ap + 8 * GSTRB);
                ah[2] = *(const uint32_t*)(ap + 8);
                ah[3] = *(const uint32_t*)(ap + 8 * GSTRB + 8);
                al[0] = *(const uint32_t*)aq;
                al[1] = *(const uint32_t*)(aq + 8 * GSTRB);
                al[2] = *(const uint32_t*)(aq + 8);
                al[3] = *(const uint32_t*)(aq + 8 * GSTRB + 8);
#pragma unroll
                for (int nt = 0; nt < 4; nt++) {
                    mma16(C[mt][nt], ah, bh[nt]);
                    mma16(C[mt][nt], al, bh[nt]);
                    mma16(C[mt][nt], ah, bl[nt]);
                }
            }
        }
    }
}

// ---------------- QKV projection -------------------------------------------
__global__ void __launch_bounds__(256, 2) qkv_bf16_kernel() {
    extern __shared__ __nv_bfloat16 smb[];
    const int z = blockIdx.z;
    const int rowBase = blockIdx.y * 128;
    const int colBase = blockIdx.x * 128;
    __nv_bfloat16* dsth = (z == 0) ? g_qh : (z == 1) ? g_kh : g_vh;
    __nv_bfloat16* dstl = (z == 0) ? g_ql : (z == 1) ? g_kl : g_vl;

    float C[4][4][4];
#pragma unroll
    for (int a = 0; a < 4; a++)
#pragma unroll
        for (int b = 0; b < 4; b++)
#pragma unroll
            for (int c = 0; c < 4; c++) C[a][b][c] = 0.f;

    gemm128_bf16(g_xh, g_xl, g_wh + (size_t)z * NW, g_wl + (size_t)z * NW,
                 rowBase, colBase, C, smb);

    const int tid = threadIdx.x;
    const int wid = tid >> 5, lane = tid & 31;
    const int g = lane >> 2, t = lane & 3;
    const int wm = (wid >> 2) * 64, wn = (wid & 3) * 32;
#pragma unroll
    for (int mt = 0; mt < 4; mt++) {
#pragma unroll
        for (int nt = 0; nt < 4; nt++) {
            int r = rowBase + wm + mt * 16 + g;
            int n = colBase + wn + nt * 8 + 2 * t;
            int h = n >> 6, d = n & 63;
            int b = r >> 11, l = r & 2047;
            size_t o0 = (((size_t)(b * Hsz + h) * Lsz + l) * HDsz + d);
            size_t o1 = (((size_t)(b * Hsz + h) * Lsz + (l + 8)) * HDsz + d);
            __nv_bfloat16 h0, l0, h1, l1;
            sbf(C[mt][nt][0], h0, l0); sbf(C[mt][nt][1], h1, l1);
            *(uint32_t*)(dsth + o0) = packbf(h0, h1);
            *(uint32_t*)(dstl + o0) = packbf(l0, l1);
            sbf(C[mt][nt][2], h0, l0); sbf(C[mt][nt][3], h1, l1);
            *(uint32_t*)(dsth + o1) = packbf(h0, h1);
            *(uint32_t*)(dstl + o1) = packbf(l0, l1);
        }
    }
}

// ---------------- Output projection ----------------------------------------
__global__ void __launch_bounds__(256, 2) oproj_bf16_kernel(float* __restrict__ out) {
    extern __shared__ __nv_bfloat16 smb[];
    const int rowBase = blockIdx.y * 128;
    const int colBase = blockIdx.x * 128;

    float C[4][4][4];
#pragma unroll
    for (int a = 0; a < 4; a++)
#pragma unroll
        for (int b = 0; b < 4; b++)
#pragma unroll
            for (int c = 0; c < 4; c++) C[a][b][c] = 0.f;

    gemm128_bf16(g_aoh, g_aol, g_wh + (size_t)3 * NW, g_wl + (size_t)3 * NW,
                 rowBase, colBase, C, smb);

    const int tid = threadIdx.x;
    const int wid = tid >> 5, lane = tid & 31;
    const int g = lane >> 2, t = lane & 3;
    const int wm = (wid >> 2) * 64, wn = (wid & 3) * 32;
#pragma unroll
    for (int mt = 0; mt < 4; mt++) {
#pragma unroll
        for (int nt = 0; nt < 4; nt++) {
            int r = rowBase + wm + mt * 16 + g;
            int n = colBase + wn + nt * 8 + 2 * t;
            *(float2*)(out + (size_t)r * Dsz + n) = make_float2(C[mt][nt][0], C[mt][nt][1]);
            *(float2*)(out + (size_t)(r + 8) * Dsz + n) = make_float2(C[mt][nt][2], C[mt][nt][3]);
        }
    }
}

// ---------------- RoPE in-place on q,k planes ------------------------------
__global__ void rope_kernel(const float* __restrict__ cosp,
                            const float* __restrict__ sinp) {
    const int idx = blockIdx.x * blockDim.x + threadIdx.x;
    const int row = idx >> 5;
    const int d = idx & 31;
    const int l = row & (Lsz - 1);

    const float c1 = cosp[l * HDsz + d];
    const float s1 = sinp[l * HDsz + d];
    const float c2 = cosp[l * HDsz + d + 32];
    const float s2 = sinp[l * HDsz + d + 32];

    const size_t a0 = (size_t)row * HDsz + d;
    const size_t a1 = a0 + 32;

    {
        float x1 = __bfloat162float(g_qh[a0]) + __bfloat162float(g_ql[a0]);
        float x2 = __bfloat162float(g_qh[a1]) + __bfloat162float(g_ql[a1]);
        float y1 = x1 * c1 - x2 * s1;
        float y2 = x2 * c2 + x1 * s2;
        __nv_bfloat16 h, lo;
        sbf(y1, h, lo); g_qh[a0] = h; g_ql[a0] = lo;
        sbf(y2, h, lo); g_qh[a1] = h; g_ql[a1] = lo;
    }
    {
        float x1 = __bfloat162float(g_kh[a0]) + __bfloat162float(g_kl[a0]);
        float x2 = __bfloat162float(g_kh[a1]) + __bfloat162float(g_kl[a1]);
        float y1 = x1 * c1 - x2 * s1;
        float y2 = x2 * c2 + x1 * s2;
        __nv_bfloat16 h, lo;
        sbf(y1, h, lo); g_kh[a0] = h; g_kl[a0] = lo;
        sbf(y2, h, lo); g_kh[a1] = h; g_kl[a1] = lo;
    }
}

// ---------------- Flash attention (bf16x3 mma) -----------------------------
// Q tile 128 x KV tile 64, 256 threads = 8 warps, warp owns 16 q rows.
// All smem planes stride 72 bf16 (144B). hi and lo planes separate.
#define FSTRB 72
#define OFF_QH 0
#define OFF_QL (128 * FSTRB)
#define OFF_KH (2 * 128 * FSTRB)
#define OFF_KL (OFF_KH + 64 * FSTRB)
#define OFF_VH (OFF_KL + 64 * FSTRB)
#define OFF_VL (OFF_VH + 64 * FSTRB)
#define OFF_PH (OFF_VL + 64 * FSTRB)
#define OFF_PL (OFF_PH + 128 * FSTRB)
#define FLASH_ELEMS (OFF_PL + 128 * FSTRB)       // 55296
#define FLASH_SMEM (FLASH_ELEMS * 2)             // 110592 bytes

__global__ void __launch_bounds__(256, 2) flashmma_kernel() {
    extern __shared__ __nv_bfloat16 smb[];
    __nv_bfloat16* Qh = smb + OFF_QH;
    __nv_bfloat16* Ql = smb + OFF_QL;
    __nv_bfloat16* Kh = smb + OFF_KH;
    __nv_bfloat16* Kl = smb + OFF_KL;
    __nv_bfloat16* Vh = smb + OFF_VH;
    __nv_bfloat16* Vl = smb + OFF_VL;
    __nv_bfloat16* Ph = smb + OFF_PH;
    __nv_bfloat16* Pl = smb + OFF_PL;

    const int tid = threadIdx.x;
    const int wid = tid >> 5, lane = tid & 31;
    const int g = lane >> 2, t = lane & 3;
    const int bh = blockIdx.y;
    const int qt = gridDim.x - 1 - blockIdx.x;      // big tiles first
    const int q0 = qt * 128;
    const size_t base = (size_t)bh * Lsz * HDsz;

    const uint32_t vh_u32 = (uint32_t)__cvta_generic_to_shared(Vh);
    const uint32_t vl_u32 = (uint32_t)__cvta_generic_to_shared(Vl);
    const int vln = lane & 15;

    // ---- load Q tile (scaled by 1/8, exact in bf16) ----
    {
        const __nv_bfloat162 s2v = __float2bfloat162_rn(0.125f);
#pragma unroll
        for (int i = 0; i < 4; i++) {
            int idx = tid + 256 * i;
            int row = idx >> 3;
            int c8 = (idx & 7) * 8;
            float4 vh4 = *(const float4*)(g_qh + base + (size_t)(q0 + row) * HDsz + c8);
            float4 vl4 = *(const float4*)(g_ql + base + (size_t)(q0 + row) * HDsz + c8);
            __nv_bfloat162* ph = (__nv_bfloat162*)&vh4;
            __nv_bfloat162* pl = (__nv_bfloat162*)&vl4;
#pragma unroll
            for (int j = 0; j < 4; j++) {
                ph[j] = __hmul2(ph[j], s2v);
                pl[j] = __hmul2(pl[j], s2v);
            }
            *(float4*)(Qh + row * FSTRB + c8) = vh4;
            *(float4*)(Ql + row * FSTRB + c8) = vl4;
        }
    }

    float O[8][4];
#pragma unroll
    for (int i = 0; i < 8; i++)
#pragma unroll
        for (int j = 0; j < 4; j++) O[i][j] = 0.f;
    float mr[2] = {-1e30f, -1e30f};
    float lr[2] = {0.f, 0.f};

    const int pr = wid * 16 + g;
    const int nkt = 2 * qt + 2;

    for (int kt = 0; kt < nkt; kt++) {
        const int j0 = kt * 64;
        __syncthreads();   // prev iter done with K/V/P (and Q stores visible on kt=0)

        // ---- load K, V hi/lo planes (plain 16B copies, coalesced) ----
#pragma unroll
        for (int i = 0; i < 2; i++) {
            int idx = tid + 256 * i;
            int row = idx >> 3;
            int c8 = (idx & 7) * 8;
            size_t go = base + (size_t)(j0 + row) * HDsz + c8;
            int so = row * FSTRB + c8;
            *(float4*)(Kh + so) = *(const float4*)(g_kh + go);
            *(float4*)(Kl + so) = *(const float4*)(g_kl + go);
            *(float4*)(Vh + so) = *(const float4*)(g_vh + go);
            *(float4*)(Vl + so) = *(const float4*)(g_vl + go);
        }
        __syncthreads();

        // ---- GEMM1: S = Q @ K^T (bf16x3) ----
        float S[8][4];
#pragma unroll
        for (int i = 0; i < 8; i++)
#pragma unroll
            for (int j = 0; j < 4; j++) S[i][j] = 0.f;

#pragma unroll
        for (int ks = 0; ks < 4; ks++) {
            const int kb = ks * 16 + 2 * t;
            const __nv_bfloat16* ap = Qh + pr * FSTRB + kb;
            const __nv_bfloat16* aq = Ql + pr * FSTRB + kb;
            uint32_t ah[4], al[4];
            ah[0] = *(const uint32_t*)ap;
            ah[1] = *(const uint32_t*)(ap + 8 * FSTRB);
            ah[2] = *(const uint32_t*)(ap + 8);
            ah[3] = *(const uint32_t*)(ap + 8 * FSTRB + 8);
            al[0] = *(const uint32_t*)aq;
            al[1] = *(const uint32_t*)(aq + 8 * FSTRB);
            al[2] = *(const uint32_t*)(aq + 8);
            al[3] = *(const uint32_t*)(aq + 8 * FSTRB + 8);
#pragma unroll
            for (int nt = 0; nt < 8; nt++) {
                const __nv_bfloat16* kp = Kh + (nt * 8 + g) * FSTRB + kb;
                const __nv_bfloat16* kq = Kl + (nt * 8 + g) * FSTRB + kb;
                uint32_t bh2[2] = {*(const uint32_t*)kp, *(const uint32_t*)(kp + 8)};
                uint32_t bl2[2] = {*(const uint32_t*)kq, *(const uint32_t*)(kq + 8)};
                mma16(S[nt], ah, bh2);
                mma16(S[nt], al, bh2);
                mma16(S[nt], ah, bl2);
            }
        }

        // ---- causal mask (diagonal tiles only) ----
        if (kt >= 2 * qt) {
            int r0g = q0 + pr;
#pragma unroll
            for (int nt = 0; nt < 8; nt++) {
                int c0 = j0 + nt * 8 + 2 * t;
                if (c0 > r0g)         S[nt][0] = -1e30f;
                if (c0 + 1 > r0g)     S[nt][1] = -1e30f;
                if (c0 > r0g + 8)     S[nt][2] = -1e30f;
                if (c0 + 1 > r0g + 8) S[nt][3] = -1e30f;
            }
        }

        // ---- online softmax ----
#pragma unroll
        for (int h2 = 0; h2 < 2; h2++) {
            float mloc = -1e30f;
#pragma unroll
            for (int nt = 0; nt < 8; nt++)
                mloc = fmaxf(mloc, fmaxf(S[nt][2 * h2], S[nt][2 * h2 + 1]));
            mloc = fmaxf(mloc, __shfl_xor_sync(0xffffffffu, mloc, 1));
            mloc = fmaxf(mloc, __shfl_xor_sync(0xffffffffu, mloc, 2));
            float mnew = fmaxf(mr[h2], mloc);
            float sc = __expf(mr[h2] - mnew);
            float ls = 0.f;
#pragma unroll
            for (int nt = 0; nt < 8; nt++) {
                float p0 = __expf(S[nt][2 * h2] - mnew);
                float p1 = __expf(S[nt][2 * h2 + 1] - mnew);
                S[nt][2 * h2] = p0; S[nt][2 * h2 + 1] = p1;
                ls += p0 + p1;
            }
            ls += __shfl_xor_sync(0xffffffffu, ls, 1);
            ls += __shfl_xor_sync(0xffffffffu, ls, 2);
            lr[h2] = lr[h2] * sc + ls;
            mr[h2] = mnew;
#pragma unroll
            for (int nt = 0; nt < 8; nt++) {
                O[nt][2 * h2] *= sc;
                O[nt][2 * h2 + 1] *= sc;
            }
        }

        // ---- store P hi/lo (warp-local rows only) ----
#pragma unroll
        for (int nt = 0; nt < 8; nt++) {
            int c = nt * 8 + 2 * t;
            __nv_bfloat16 h0, l0, h1, l1;
            sbf(S[nt][0], h0, l0); sbf(S[nt][1], h1, l1);
            *(uint32_t*)(Ph + pr * FSTRB + c) = packbf(h0, h1);
            *(uint32_t*)(Pl + pr * FSTRB + c) = packbf(l0, l1);
            sbf(S[nt][2], h0, l0); sbf(S[nt][3], h1, l1);
            *(uint32_t*)(Ph + (pr + 8) * FSTRB + c) = packbf(h0, h1);
            *(uint32_t*)(Pl + (pr + 8) * FSTRB + c) = packbf(l0, l1);
        }
        __syncwarp();

        // ---- GEMM2: O += P @ V (V via ldmatrix.trans) ----
#pragma unroll
        for (int ks = 0; ks < 4; ks++) {
            const int kb = ks * 16 + 2 * t;
            const __nv_bfloat16* ap = Ph + pr * FSTRB + kb;
            const __nv_bfloat16* aq = Pl + pr * FSTRB + kb;
            uint32_t ah[4], al[4];
            ah[0] = *(const uint32_t*)ap;
            ah[1] = *(const uint32_t*)(ap + 8 * FSTRB);
            ah[2] = *(const uint32_t*)(ap + 8);
            ah[3] = *(const uint32_t*)(ap + 8 * FSTRB + 8);
            al[0] = *(const uint32_t*)aq;
            al[1] = *(const uint32_t*)(aq + 8 * FSTRB);
            al[2] = *(const uint32_t*)(aq + 8);
            al[3] = *(const uint32_t*)(aq + 8 * FSTRB + 8);

            const uint32_t rowoff = ((ks * 16 + vln) * FSTRB) * 2;
#pragma unroll
            for (int dt = 0; dt < 8; dt++) {
                uint32_t bh2[2], bl2[2];
                ldsm_x2_trans(bh2[0], bh2[1], vh_u32 + rowoff + dt * 16);
                ldsm_x2_trans(bl2[0], bl2[1], vl_u32 + rowoff + dt * 16);
                mma16(O[dt], ah, bh2);
                mma16(O[dt], al, bh2);
                mma16(O[dt], ah, bl2);
            }
        }
    }

    // ---- epilogue: normalize, split, write ao planes ----
    const float i0 = 1.f / lr[0];
    const float i1 = 1.f / lr[1];
    const int r = q0 + pr;
    const int b = bh >> 4;
    const int h = bh & 15;
    const size_t ob = (size_t)b * Lsz * Dsz + (size_t)h * HDsz;
#pragma unroll
    for (int dt = 0; dt < 8; dt++) {
        int d = dt * 8 + 2 * t;
        __nv_bfloat16 h0, l0, h1, l1;
        sbf(O[dt][0] * i0, h0, l0); sbf(O[dt][1] * i0, h1, l1);
        *(uint32_t*)(g_aoh + ob + (size_t)r * Dsz + d) = packbf(h0, h1);
        *(uint32_t*)(g_aol + ob + (size_t)r * Dsz + d) = packbf(l0, l1);
        sbf(O[dt][2] * i1, h0, l0); sbf(O[dt][3] * i1, h1, l1);
        *(uint32_t*)(g_aoh + ob + (size_t)(r + 8) * Dsz + d) = packbf(h0, h1);
        *(uint32_t*)(g_aol + ob + (size_t)(r + 8) * Dsz + d) = packbf(l0, l1);
    }
}

// ---------------------------------------------------------------------------
extern "C" void kernel_launch(void* const* d_in, const int* in_sizes, int n_in,
                              void* d_out, int out_size) {
    (void)in_sizes; (void)n_in; (void)out_size;
    const float* x    = (const float*)d_in[0];
    const float* cosp = (const float*)d_in[1];
    const float* sinp = (const float*)d_in[2];
    const float* wq   = (const float*)d_in[3];
    const float* wk   = (const float*)d_in[4];
    const float* wv   = (const float*)d_in[5];
    const float* wo   = (const float*)d_in[6];
    float* out = (float*)d_out;

    cudaFuncSetAttribute(qkv_bf16_kernel,
                         cudaFuncAttributeMaxDynamicSharedMemorySize, GEMM_SMEM);
    cudaFuncSetAttribute(oproj_bf16_kernel,
                         cudaFuncAttributeMaxDynamicSharedMemorySize, GEMM_SMEM);
    cudaFuncSetAttribute(flashmma_kernel,
                         cudaFuncAttributeMaxDynamicSharedMemorySize, FLASH_SMEM);

    // 1) split inputs into bf16 hi/lo planes
    split_x_kernel<<<(NX / 2) / 256, 256>>>(x);
    split_w_kernel<<<(4 * NW / 2) / 256, 256>>>(wq, wk, wv, wo);

    // 2) QKV projections -> q/k/v planes [B,H,L,hd]
    qkv_bf16_kernel<<<dim3(Dsz / 128, (Bsz * Lsz) / 128, 3), 256, GEMM_SMEM>>>();

    // 3) RoPE in place on q,k planes
    rope_kernel<<<(Bsz * Hsz * Lsz * 32) / 256, 256>>>(cosp, sinp);

    // 4) causal flash attention -> ao planes
    flashmma_kernel<<<dim3(Lsz / 128, Bsz * Hsz), 256, FLASH_SMEM>>>();

    // 5) output projection -> d_out
    oproj_bf16_kernel<<<dim3(Dsz / 128, (Bsz * Lsz) / 128), 256, GEMM_SMEM>>>(out);
}

// round 7
// speedup vs baseline: 2.9783x; 1.0098x over previous
#include <cuda_runtime.h>
#include <cuda_bf16.h>
#include <math.h>
#include <stdint.h>

// Problem constants: B=2, L=2048, D=1024, H=16, hd=64
#define Bsz 2
#define Lsz 2048
#define Dsz 1024
#define Hsz 16
#define HDsz 64

#define NQKV (Bsz * Hsz * Lsz * HDsz)   // 4194304
#define NX   (Bsz * Lsz * Dsz)          // 4194304
#define NW   (Dsz * Dsz)                // 1048576 = 2^20

// ---------------- device scratch: bf16 hi/lo planes ------------------------
__device__ __nv_bfloat16 g_xh[NX],  g_xl[NX];
__device__ __nv_bfloat16 g_wh[4 * NW], g_wl[4 * NW];
__device__ __nv_bfloat16 g_qh[NQKV], g_ql[NQKV];
__device__ __nv_bfloat16 g_kh[NQKV], g_kl[NQKV];
__device__ __nv_bfloat16 g_vh[NQKV], g_vl[NQKV];
__device__ __nv_bfloat16 g_aoh[NX], g_aol[NX];

// ---------------- helpers --------------------------------------------------
__device__ __forceinline__ void sbf(float x, __nv_bfloat16& h, __nv_bfloat16& l) {
    h = __float2bfloat16(x);
    l = __float2bfloat16(x - __bfloat162float(h));
}
__device__ __forceinline__ uint32_t packbf(__nv_bfloat16 a, __nv_bfloat16 b) {
    uint16_t au = *(uint16_t*)&a, bu = *(uint16_t*)&b;
    return (uint32_t)au | ((uint32_t)bu << 16);
}

__device__ __forceinline__ void mma16(float c[4], const uint32_t a[4], const uint32_t b[2]) {
    asm volatile(
        "mma.sync.aligned.m16n8k16.row.col.f32.bf16.bf16.f32 "
        "{%0,%1,%2,%3}, {%4,%5,%6,%7}, {%8,%9}, {%0,%1,%2,%3};\n"
        : "+f"(c[0]), "+f"(c[1]), "+f"(c[2]), "+f"(c[3])
        : "r"(a[0]), "r"(a[1]), "r"(a[2]), "r"(a[3]), "r"(b[0]), "r"(b[1]));
}

__device__ __forceinline__ void ldsm_x2_trans(uint32_t& r0, uint32_t& r1, uint32_t addr) {
    asm volatile("ldmatrix.sync.aligned.m8n8.x2.trans.shared.b16 {%0,%1}, [%2];"
                 : "=r"(r0), "=r"(r1) : "r"(addr));
}

__device__ __forceinline__ void cp16(uint32_t dst, const void* src) {
    asm volatile("cp.async.cg.shared.global [%0],[%1],16;\n" ::"r"(dst), "l"(src) : "memory");
}
__device__ __forceinline__ void cpcommit() { asm volatile("cp.async.commit_group;\n" ::: "memory"); }
__device__ __forceinline__ void cpwait1()  { asm volatile("cp.async.wait_group 1;\n" ::: "memory"); }
__device__ __forceinline__ void cpwait0()  { asm volatile("cp.async.wait_group 0;\n" ::: "memory"); }

// ---------------- split kernels: fp32 -> bf16 hi/lo planes -----------------
__global__ void split_x_kernel(const float* __restrict__ in) {
    int i = blockIdx.x * blockDim.x + threadIdx.x;
    float2 v = *(const float2*)(in + 2 * (size_t)i);
    __nv_bfloat16 h0, l0, h1, l1;
    sbf(v.x, h0, l0); sbf(v.y, h1, l1);
    ((uint32_t*)g_xh)[i] = packbf(h0, h1);
    ((uint32_t*)g_xl)[i] = packbf(l0, l1);
}

__global__ void split_w_kernel(const float* __restrict__ wq,
                               const float* __restrict__ wk,
                               const float* __restrict__ wv,
                               const float* __restrict__ wo) {
    int i = blockIdx.x * blockDim.x + threadIdx.x;
    size_t e = 2 * (size_t)i;
    int m = (int)(e >> 20);
    int r = (int)(e & (NW - 1));
    const float* src = (m == 0) ? wq : (m == 1) ? wk : (m == 2) ? wv : wo;
    float2 v = *(const float2*)(src + r);
    __nv_bfloat16 h0, l0, h1, l1;
    sbf(v.x, h0, l0); sbf(v.y, h1, l1);
    ((uint32_t*)g_wh)[((size_t)m * NW + r) >> 1] = packbf(h0, h1);
    ((uint32_t*)g_wl)[((size_t)m * NW + r) >> 1] = packbf(l0, l1);
}

// ---------------- bf16x3 projection GEMM (128x256 CTA tile) ----------------
// C = A @ W^T, K=1024 in 32 chunks of 32. 256 threads = 8 warps (2 M x 4 N),
// warp tile 64x64. 3-stage cp.async pipeline.
// Stage layout: [Ah | Al | Bh | Bl] with Ah/Al = PA_ELEMS, Bh/Bl = PB_ELEMS.
#define PSTR 40                                   // 32 data + 8 pad bf16
#define PA_ELEMS (128 * PSTR)                     // 5120
#define PB_ELEMS (256 * PSTR)                     // 10240
#define PSTAGE_ELEMS (2 * PA_ELEMS + 2 * PB_ELEMS)  // 30720 bf16
#define PSTAGE_BYTES (PSTAGE_ELEMS * 2)           // 61440
#define PROJ_SMEM (3 * PSTAGE_BYTES)              // 184320 bytes

__device__ __forceinline__ void proj_mainloop(const __nv_bfloat16* __restrict__ Agh,
                                              const __nv_bfloat16* __restrict__ Agl,
                                              const __nv_bfloat16* __restrict__ Bgh,
                                              const __nv_bfloat16* __restrict__ Bgl,
                                              float C[4][8][4], __nv_bfloat16* sm) {
    const int tid = threadIdx.x;
    const int wid = tid >> 5, lane = tid & 31;
    const int g = lane >> 2, t = lane & 3;
    const int wm = (wid >> 2) * 64;               // 0 or 64
    const int wn = (wid & 3) * 64;                // 0..192

    auto load_chunk = [&](int c, int s) {
        __nv_bfloat16* st = sm + s * PSTAGE_ELEMS;
        // A hi/lo: 128 rows x 32 cols
#pragma unroll
        for (int p = 0; p < 2; p++) {
            const __nv_bfloat16* gp = (p == 0) ? Agh : Agl;
            __nv_bfloat16* sp = st + p * PA_ELEMS;
#pragma unroll
            for (int i = 0; i < 2; i++) {
                int idx = tid + 256 * i;          // 0..511
                int row = idx >> 2, q = idx & 3;
                cp16((uint32_t)__cvta_generic_to_shared(sp + row * PSTR + q * 8),
                     gp + (size_t)row * Dsz + c * 32 + q * 8);
            }
        }
        // B hi/lo: 256 rows x 32 cols
#pragma unroll
        for (int p = 0; p < 2; p++) {
            const __nv_bfloat16* gp = (p == 0) ? Bgh : Bgl;
            __nv_bfloat16* sp = st + 2 * PA_ELEMS + p * PB_ELEMS;
#pragma unroll
            for (int i = 0; i < 4; i++) {
                int idx = tid + 256 * i;          // 0..1023
                int row = idx >> 2, q = idx & 3;
                cp16((uint32_t)__cvta_generic_to_shared(sp + row * PSTR + q * 8),
                     gp + (size_t)row * Dsz + c * 32 + q * 8);
            }
        }
    };

    const int NCH = Dsz / 32;                     // 32
    load_chunk(0, 0); cpcommit();
    load_chunk(1, 1); cpcommit();

    for (int c = 0; c < NCH; c++) {
        if (c == NCH - 1) cpwait0(); else cpwait1();
        __syncthreads();
        if (c + 2 < NCH) { load_chunk(c + 2, (c + 2) % 3); cpcommit(); }

        const __nv_bfloat16* st = sm + (c % 3) * PSTAGE_ELEMS;
        const __nv_bfloat16* sAh = st;
        const __nv_bfloat16* sAl = st + PA_ELEMS;
        const __nv_bfloat16* sBh = st + 2 * PA_ELEMS;
        const __nv_bfloat16* sBl = st + 2 * PA_ELEMS + PB_ELEMS;   // FIXED (was 3*PA_ELEMS)

#pragma unroll
        for (int ks = 0; ks < 2; ks++) {
            const int kb = ks * 16 + 2 * t;
            uint32_t bh[8][2], bl[8][2];
#pragma unroll
            for (int nt = 0; nt < 8; nt++) {
                const __nv_bfloat16* bp = sBh + (wn + nt * 8 + g) * PSTR + kb;
                const __nv_bfloat16* bq = sBl + (wn + nt * 8 + g) * PSTR + kb;
                bh[nt][0] = *(const uint32_t*)bp;
                bh[nt][1] = *(const uint32_t*)(bp + 8);
                bl[nt][0] = *(const uint32_t*)bq;
                bl[nt][1] = *(const uint32_t*)(bq + 8);
            }
#pragma unroll
            for (int mt = 0; mt < 4; mt++) {
                const int ar = wm + mt * 16 + g;
                const __nv_bfloat16* ap = sAh + ar * PSTR + kb;
                const __nv_bfloat16* aq = sAl + ar * PSTR + kb;
                uint32_t ah[4], al[4];
                ah[0] = *(const uint32_t*)ap;
                ah[1] = *(const uint32_t*)(ap + 8 * PSTR);
                ah[2] = *(const uint32_t*)(ap + 8);
                ah[3] = *(const uint32_t*)(ap + 8 * PSTR + 8);
                al[0] = *(const uint32_t*)aq;
                al[1] = *(const uint32_t*)(aq + 8 * PSTR);
                al[2] = *(const uint32_t*)(aq + 8);
                al[3] = *(const uint32_t*)(aq + 8 * PSTR + 8);
#pragma unroll
                for (int nt = 0; nt < 8; nt++) {
                    mma16(C[mt][nt], ah, bh[nt]);
                    mma16(C[mt][nt], al, bh[nt]);
                    mma16(C[mt][nt], ah, bl[nt]);
                }
            }
        }
    }
}

// ---------------- QKV projection (writes bf16 hi/lo q/k/v planes) ----------
__global__ void __launch_bounds__(256, 1) qkv_bf16_kernel() {
    extern __shared__ __nv_bfloat16 smb[];
    const int z = blockIdx.z;
    const int rowBase = blockIdx.y * 128;
    const int colBase = blockIdx.x * 256;
    __nv_bfloat16* dsth = (z == 0) ? g_qh : (z == 1) ? g_kh : g_vh;
    __nv_bfloat16* dstl = (z == 0) ? g_ql : (z == 1) ? g_kl : g_vl;

    float C[4][8][4];
#pragma unroll
    for (int a = 0; a < 4; a++)
#pragma unroll
        for (int b = 0; b < 8; b++)
#pragma unroll
            for (int c = 0; c < 4; c++) C[a][b][c] = 0.f;

    proj_mainloop(g_xh + (size_t)rowBase * Dsz, g_xl + (size_t)rowBase * Dsz,
                  g_wh + (size_t)z * NW + (size_t)colBase * Dsz,
                  g_wl + (size_t)z * NW + (size_t)colBase * Dsz, C, smb);

    const int tid = threadIdx.x;
    const int wid = tid >> 5, lane = tid & 31;
    const int g = lane >> 2, t = lane & 3;
    const int wm = (wid >> 2) * 64, wn = (wid & 3) * 64;
#pragma unroll
    for (int mt = 0; mt < 4; mt++) {
#pragma unroll
        for (int nt = 0; nt < 8; nt++) {
            int r = rowBase + wm + mt * 16 + g;
            int n = colBase + wn + nt * 8 + 2 * t;
            int h = n >> 6, d = n & 63;
            int b = r >> 11, l = r & 2047;
            size_t o0 = (((size_t)(b * Hsz + h) * Lsz + l) * HDsz + d);
            size_t o1 = (((size_t)(b * Hsz + h) * Lsz + (l + 8)) * HDsz + d);
            __nv_bfloat16 h0, l0, h1, l1;
            sbf(C[mt][nt][0], h0, l0); sbf(C[mt][nt][1], h1, l1);
            *(uint32_t*)(dsth + o0) = packbf(h0, h1);
            *(uint32_t*)(dstl + o0) = packbf(l0, l1);
            sbf(C[mt][nt][2], h0, l0); sbf(C[mt][nt][3], h1, l1);
            *(uint32_t*)(dsth + o1) = packbf(h0, h1);
            *(uint32_t*)(dstl + o1) = packbf(l0, l1);
        }
    }
}

// ---------------- Output projection (writes fp32 out) ----------------------
__global__ void __launch_bounds__(256, 1) oproj_bf16_kernel(float* __restrict__ out) {
    extern __shared__ __nv_bfloat16 smb[];
    const int rowBase = blockIdx.y * 128;
    const int colBase = blockIdx.x * 256;

    float C[4][8][4];
#pragma unroll
    for (int a = 0; a < 4; a++)
#pragma unroll
        for (int b = 0; b < 8; b++)
#pragma unroll
            for (int c = 0; c < 4; c++) C[a][b][c] = 0.f;

    proj_mainloop(g_aoh + (size_t)rowBase * Dsz, g_aol + (size_t)rowBase * Dsz,
                  g_wh + (size_t)3 * NW + (size_t)colBase * Dsz,
                  g_wl + (size_t)3 * NW + (size_t)colBase * Dsz, C, smb);

    const int tid = threadIdx.x;
    const int wid = tid >> 5, lane = tid & 31;
    const int g = lane >> 2, t = lane & 3;
    const int wm = (wid >> 2) * 64, wn = (wid & 3) * 64;
#pragma unroll
    for (int mt = 0; mt < 4; mt++) {
#pragma unroll
        for (int nt = 0; nt < 8; nt++) {
            int r = rowBase + wm + mt * 16 + g;
            int n = colBase + wn + nt * 8 + 2 * t;
            *(float2*)(out + (size_t)r * Dsz + n) = make_float2(C[mt][nt][0], C[mt][nt][1]);
            *(float2*)(out + (size_t)(r + 8) * Dsz + n) = make_float2(C[mt][nt][2], C[mt][nt][3]);
        }
    }
}

// ---------------- RoPE in-place on q,k planes ------------------------------
__global__ void rope_kernel(const float* __restrict__ cosp,
                            const float* __restrict__ sinp) {
    const int idx = blockIdx.x * blockDim.x + threadIdx.x;
    const int row = idx >> 5;
    const int d = idx & 31;
    const int l = row & (Lsz - 1);

    const float c1 = cosp[l * HDsz + d];
    const float s1 = sinp[l * HDsz + d];
    const float c2 = cosp[l * HDsz + d + 32];
    const float s2 = sinp[l * HDsz + d + 32];

    const size_t a0 = (size_t)row * HDsz + d;
    const size_t a1 = a0 + 32;

    {
        float x1 = __bfloat162float(g_qh[a0]) + __bfloat162float(g_ql[a0]);
        float x2 = __bfloat162float(g_qh[a1]) + __bfloat162float(g_ql[a1]);
        float y1 = x1 * c1 - x2 * s1;
        float y2 = x2 * c2 + x1 * s2;
        __nv_bfloat16 h, lo;
        sbf(y1, h, lo); g_qh[a0] = h; g_ql[a0] = lo;
        sbf(y2, h, lo); g_qh[a1] = h; g_ql[a1] = lo;
    }
    {
        float x1 = __bfloat162float(g_kh[a0]) + __bfloat162float(g_kl[a0]);
        float x2 = __bfloat162float(g_kh[a1]) + __bfloat162float(g_kl[a1]);
        float y1 = x1 * c1 - x2 * s1;
        float y2 = x2 * c2 + x1 * s2;
        __nv_bfloat16 h, lo;
        sbf(y1, h, lo); g_kh[a0] = h; g_kl[a0] = lo;
        sbf(y2, h, lo); g_kh[a1] = h; g_kl[a1] = lo;
    }
}

// ---------------- Flash attention (bf16x3 mma.sync) ------------------------
#define FSTRB 72
#define OFF_QH 0
#define OFF_QL (128 * FSTRB)
#define OFF_KH (2 * 128 * FSTRB)
#define OFF_KL (OFF_KH + 64 * FSTRB)
#define OFF_VH (OFF_KL + 64 * FSTRB)
#define OFF_VL (OFF_VH + 64 * FSTRB)
#define OFF_PH (OFF_VL + 64 * FSTRB)
#define OFF_PL (OFF_PH + 128 * FSTRB)
#define FLASH_ELEMS (OFF_PL + 128 * FSTRB)
#define FLASH_SMEM (FLASH_ELEMS * 2)             // 110592 bytes

__global__ void __launch_bounds__(256, 2) flashmma_kernel() {
    extern __shared__ __nv_bfloat16 smb[];
    __nv_bfloat16* Qh = smb + OFF_QH;
    __nv_bfloat16* Ql = smb + OFF_QL;
    __nv_bfloat16* Kh = smb + OFF_KH;
    __nv_bfloat16* Kl = smb + OFF_KL;
    __nv_bfloat16* Vh = smb + OFF_VH;
    __nv_bfloat16* Vl = smb + OFF_VL;
    __nv_bfloat16* Ph = smb + OFF_PH;
    __nv_bfloat16* Pl = smb + OFF_PL;

    const int tid = threadIdx.x;
    const int wid = tid >> 5, lane = tid & 31;
    const int g = lane >> 2, t = lane & 3;
    const int bh = blockIdx.y;
    const int qt = gridDim.x - 1 - blockIdx.x;
    const int q0 = qt * 128;
    const size_t base = (size_t)bh * Lsz * HDsz;

    const uint32_t vh_u32 = (uint32_t)__cvta_generic_to_shared(Vh);
    const uint32_t vl_u32 = (uint32_t)__cvta_generic_to_shared(Vl);
    const int vln = lane & 15;

    {
        const __nv_bfloat162 s2v = __float2bfloat162_rn(0.125f);
#pragma unroll
        for (int i = 0; i < 4; i++) {
            int idx = tid + 256 * i;
            int row = idx >> 3;
            int c8 = (idx & 7) * 8;
            float4 vh4 = *(const float4*)(g_qh + base + (size_t)(q0 + row) * HDsz + c8);
            float4 vl4 = *(const float4*)(g_ql + base + (size_t)(q0 + row) * HDsz + c8);
            __nv_bfloat162* ph = (__nv_bfloat162*)&vh4;
            __nv_bfloat162* pl = (__nv_bfloat162*)&vl4;
#pragma unroll
            for (int j = 0; j < 4; j++) {
                ph[j] = __hmul2(ph[j], s2v);
                pl[j] = __hmul2(pl[j], s2v);
            }
            *(float4*)(Qh + row * FSTRB + c8) = vh4;
            *(float4*)(Ql + row * FSTRB + c8) = vl4;
        }
    }

    float O[8][4];
#pragma unroll
    for (int i = 0; i < 8; i++)
#pragma unroll
        for (int j = 0; j < 4; j++) O[i][j] = 0.f;
    float mr[2] = {-1e30f, -1e30f};
    float lr[2] = {0.f, 0.f};

    const int pr = wid * 16 + g;
    const int nkt = 2 * qt + 2;

    for (int kt = 0; kt < nkt; kt++) {
        const int j0 = kt * 64;
        __syncthreads();

#pragma unroll
        for (int i = 0; i < 2; i++) {
            int idx = tid + 256 * i;
            int row = idx >> 3;
            int c8 = (idx & 7) * 8;
            size_t go = base + (size_t)(j0 + row) * HDsz + c8;
            int so = row * FSTRB + c8;
            *(float4*)(Kh + so) = *(const float4*)(g_kh + go);
            *(float4*)(Kl + so) = *(const float4*)(g_kl + go);
            *(float4*)(Vh + so) = *(const float4*)(g_vh + go);
            *(float4*)(Vl + so) = *(const float4*)(g_vl + go);
        }
        __syncthreads();

        float S[8][4];
#pragma unroll
        for (int i = 0; i < 8; i++)
#pragma unroll
            for (int j = 0; j < 4; j++) S[i][j] = 0.f;

#pragma unroll
        for (int ks = 0; ks < 4; ks++) {
            const int kb = ks * 16 + 2 * t;
            const __nv_bfloat16* ap = Qh + pr * FSTRB + kb;
            const __nv_bfloat16* aq = Ql + pr * FSTRB + kb;
            uint32_t ah[4], al[4];
            ah[0] = *(const uint32_t*)ap;
            ah[1] = *(const uint32_t*)(ap + 8 * FSTRB);
            ah[2] = *(const uint32_t*)(ap + 8);
            ah[3] = *(const uint32_t*)(ap + 8 * FSTRB + 8);
            al[0] = *(const uint32_t*)aq;
            al[1] = *(const uint32_t*)(aq + 8 * FSTRB);
            al[2] = *(const uint32_t*)(aq + 8);
            al[3] = *(const uint32_t*)(aq + 8 * FSTRB + 8);
#pragma unroll
            for (int nt = 0; nt < 8; nt++) {
                const __nv_bfloat16* kp = Kh + (nt * 8 + g) * FSTRB + kb;
                const __nv_bfloat16* kq = Kl + (nt * 8 + g) * FSTRB + kb;
                uint32_t bh2[2] = {*(const uint32_t*)kp, *(const uint32_t*)(kp + 8)};
                uint32_t bl2[2] = {*(const uint32_t*)kq, *(const uint32_t*)(kq + 8)};
                mma16(S[nt], ah, bh2);
                mma16(S[nt], al, bh2);
                mma16(S[nt], ah, bl2);
            }
        }

        if (kt >= 2 * qt) {
            int r0g = q0 + pr;
#pragma unroll
            for (int nt = 0; nt < 8; nt++) {
                int c0 = j0 + nt * 8 + 2 * t;
                if (c0 > r0g)         S[nt][0] = -1e30f;
                if (c0 + 1 > r0g)     S[nt][1] = -1e30f;
                if (c0 > r0g + 8)     S[nt][2] = -1e30f;
                if (c0 + 1 > r0g + 8) S[nt][3] = -1e30f;
            }
        }

#pragma unroll
        for (int h2 = 0; h2 < 2; h2++) {
            float mloc = -1e30f;
#pragma unroll
            for (int nt = 0; nt < 8; nt++)
                mloc = fmaxf(mloc, fmaxf(S[nt][2 * h2], S[nt][2 * h2 + 1]));
            mloc = fmaxf(mloc, __shfl_xor_sync(0xffffffffu, mloc, 1));
            mloc = fmaxf(mloc, __shfl_xor_sync(0xffffffffu, mloc, 2));
            float mnew = fmaxf(mr[h2], mloc);
            float sc = __expf(mr[h2] - mnew);
            float ls = 0.f;
#pragma unroll
            for (int nt = 0; nt < 8; nt++) {
                float p0 = __expf(S[nt][2 * h2] - mnew);
                float p1 = __expf(S[nt][2 * h2 + 1] - mnew);
                S[nt][2 * h2] = p0; S[nt][2 * h2 + 1] = p1;
                ls += p0 + p1;
            }
            ls += __shfl_xor_sync(0xffffffffu, ls, 1);
            ls += __shfl_xor_sync(0xffffffffu, ls, 2);
            lr[h2] = lr[h2] * sc + ls;
            mr[h2] = mnew;
#pragma unroll
            for (int nt = 0; nt < 8; nt++) {
                O[nt][2 * h2] *= sc;
                O[nt][2 * h2 + 1] *= sc;
            }
        }

#pragma unroll
        for (int nt = 0; nt < 8; nt++) {
            int c = nt * 8 + 2 * t;
            __nv_bfloat16 h0, l0, h1, l1;
            sbf(S[nt][0], h0, l0); sbf(S[nt][1], h1, l1);
            *(uint32_t*)(Ph + pr * FSTRB + c) = packbf(h0, h1);
            *(uint32_t*)(Pl + pr * FSTRB + c) = packbf(l0, l1);
            sbf(S[nt][2], h0, l0); sbf(S[nt][3], h1, l1);
            *(uint32_t*)(Ph + (pr + 8) * FSTRB + c) = packbf(h0, h1);
            *(uint32_t*)(Pl + (pr + 8) * FSTRB + c) = packbf(l0, l1);
        }
        __syncwarp();

#pragma unroll
        for (int ks = 0; ks < 4; ks++) {
            const int kb = ks * 16 + 2 * t;
            const __nv_bfloat16* ap = Ph + pr * FSTRB + kb;
            const __nv_bfloat16* aq = Pl + pr * FSTRB + kb;
            uint32_t ah[4], al[4];
            ah[0] = *(const uint32_t*)ap;
            ah[1] = *(const uint32_t*)(ap + 8 * FSTRB);
            ah[2] = *(const uint32_t*)(ap + 8);
            ah[3] = *(const uint32_t*)(ap + 8 * FSTRB + 8);
            al[0] = *(const uint32_t*)aq;
            al[1] = *(const uint32_t*)(aq + 8 * FSTRB);
            al[2] = *(const uint32_t*)(aq + 8);
            al[3] = *(const uint32_t*)(aq + 8 * FSTRB + 8);

            const uint32_t rowoff = ((ks * 16 + vln) * FSTRB) * 2;
#pragma unroll
            for (int dt = 0; dt < 8; dt++) {
                uint32_t bh2[2], bl2[2];
                ldsm_x2_trans(bh2[0], bh2[1], vh_u32 + rowoff + dt * 16);
                ldsm_x2_trans(bl2[0], bl2[1], vl_u32 + rowoff + dt * 16);
                mma16(O[dt], ah, bh2);
                mma16(O[dt], al, bh2);
                mma16(O[dt], ah, bl2);
            }
        }
    }

    const float i0 = 1.f / lr[0];
    const float i1 = 1.f / lr[1];
    const int r = q0 + pr;
    const int b = bh >> 4;
    const int h = bh & 15;
    const size_t ob = (size_t)b * Lsz * Dsz + (size_t)h * HDsz;
#pragma unroll
    for (int dt = 0; dt < 8; dt++) {
        int d = dt * 8 + 2 * t;
        __nv_bfloat16 h0, l0, h1, l1;
        sbf(O[dt][0] * i0, h0, l0); sbf(O[dt][1] * i0, h1, l1);
        *(uint32_t*)(g_aoh + ob + (size_t)r * Dsz + d) = packbf(h0, h1);
        *(uint32_t*)(g_aol + ob + (size_t)r * Dsz + d) = packbf(l0, l1);
        sbf(O[dt][2] * i1, h0, l0); sbf(O[dt][3] * i1, h1, l1);
        *(uint32_t*)(g_aoh + ob + (size_t)(r + 8) * Dsz + d) = packbf(h0, h1);
        *(uint32_t*)(g_aol + ob + (size_t)(r + 8) * Dsz + d) = packbf(l0, l1);
    }
}

// ---------------------------------------------------------------------------
extern "C" void kernel_launch(void* const* d_in, const int* in_sizes, int n_in,
                              void* d_out, int out_size) {
    (void)in_sizes; (void)n_in; (void)out_size;
    const float* x    = (const float*)d_in[0];
    const float* cosp = (const float*)d_in[1];
    const float* sinp = (const float*)d_in[2];
    const float* wq   = (const float*)d_in[3];
    const float* wk   = (const float*)d_in[4];
    const float* wv   = (const float*)d_in[5];
    const float* wo   = (const float*)d_in[6];
    float* out = (float*)d_out;

    cudaFuncSetAttribute(qkv_bf16_kernel,
                         cudaFuncAttributeMaxDynamicSharedMemorySize, PROJ_SMEM);
    cudaFuncSetAttribute(oproj_bf16_kernel,
                         cudaFuncAttributeMaxDynamicSharedMemorySize, PROJ_SMEM);
    cudaFuncSetAttribute(flashmma_kernel,
                         cudaFuncAttributeMaxDynamicSharedMemorySize, FLASH_SMEM);

    // 1) split inputs into bf16 hi/lo planes
    split_x_kernel<<<(NX / 2) / 256, 256>>>(x);
    split_w_kernel<<<(4 * NW / 2) / 256, 256>>>(wq, wk, wv, wo);

    // 2) QKV projections -> q/k/v planes [B,H,L,hd]
    qkv_bf16_kernel<<<dim3(Dsz / 256, (Bsz * Lsz) / 128, 3), 256, PROJ_SMEM>>>();

    // 3) RoPE in place on q,k planes
    rope_kernel<<<(Bsz * Hsz * Lsz * 32) / 256, 256>>>(cosp, sinp);

    // 4) causal flash attention -> ao planes
    flashmma_kernel<<<dim3(Lsz / 128, Bsz * Hsz), 256, FLASH_SMEM>>>();

    // 5) output projection -> d_out
    oproj_bf16_kernel<<<dim3(Dsz / 256, (Bsz * Lsz) / 128), 256, PROJ_SMEM>>>(out);
}

// round 8
// speedup vs baseline: 3.2206x; 1.0814x over previous
#include <cuda_runtime.h>
#include <cuda_bf16.h>
#include <math.h>
#include <stdint.h>

// Problem constants: B=2, L=2048, D=1024, H=16, hd=64
#define Bsz 2
#define Lsz 2048
#define Dsz 1024
#define Hsz 16
#define HDsz 64

#define NQKV (Bsz * Hsz * Lsz * HDsz)   // 4194304
#define NX   (Bsz * Lsz * Dsz)          // 4194304
#define NW   (Dsz * Dsz)                // 1048576 = 2^20

// ---------------- device scratch: bf16 hi/lo planes ------------------------
__device__ __nv_bfloat16 g_xh[NX],  g_xl[NX];
__device__ __nv_bfloat16 g_wh[4 * NW], g_wl[4 * NW];
__device__ __nv_bfloat16 g_qh[NQKV], g_ql[NQKV];
__device__ __nv_bfloat16 g_kh[NQKV], g_kl[NQKV];
__device__ __nv_bfloat16 g_vh[NQKV], g_vl[NQKV];
__device__ __nv_bfloat16 g_aoh[NX], g_aol[NX];

// ---------------- helpers --------------------------------------------------
__device__ __forceinline__ void sbf(float x, __nv_bfloat16& h, __nv_bfloat16& l) {
    h = __float2bfloat16(x);
    l = __float2bfloat16(x - __bfloat162float(h));
}
__device__ __forceinline__ uint32_t packbf(__nv_bfloat16 a, __nv_bfloat16 b) {
    uint16_t au = *(uint16_t*)&a, bu = *(uint16_t*)&b;
    return (uint32_t)au | ((uint32_t)bu << 16);
}

__device__ __forceinline__ void mma16(float c[4], const uint32_t a[4], const uint32_t b[2]) {
    asm volatile(
        "mma.sync.aligned.m16n8k16.row.col.f32.bf16.bf16.f32 "
        "{%0,%1,%2,%3}, {%4,%5,%6,%7}, {%8,%9}, {%0,%1,%2,%3};\n"
        : "+f"(c[0]), "+f"(c[1]), "+f"(c[2]), "+f"(c[3])
        : "r"(a[0]), "r"(a[1]), "r"(a[2]), "r"(a[3]), "r"(b[0]), "r"(b[1]));
}

__device__ __forceinline__ void ldsm_x2_trans(uint32_t& r0, uint32_t& r1, uint32_t addr) {
    asm volatile("ldmatrix.sync.aligned.m8n8.x2.trans.shared.b16 {%0,%1}, [%2];"
                 : "=r"(r0), "=r"(r1) : "r"(addr));
}

__device__ __forceinline__ void cp16(uint32_t dst, const void* src) {
    asm volatile("cp.async.cg.shared.global [%0],[%1],16;\n" ::"r"(dst), "l"(src) : "memory");
}
__device__ __forceinline__ void cpcommit() { asm volatile("cp.async.commit_group;\n" ::: "memory"); }
__device__ __forceinline__ void cpwait1()  { asm volatile("cp.async.wait_group 1;\n" ::: "memory"); }
__device__ __forceinline__ void cpwait0()  { asm volatile("cp.async.wait_group 0;\n" ::: "memory"); }

// ---------------- split kernels: fp32 -> bf16 hi/lo planes -----------------
__global__ void split_x_kernel(const float* __restrict__ in) {
    int i = blockIdx.x * blockDim.x + threadIdx.x;
    float2 v = *(const float2*)(in + 2 * (size_t)i);
    __nv_bfloat16 h0, l0, h1, l1;
    sbf(v.x, h0, l0); sbf(v.y, h1, l1);
    ((uint32_t*)g_xh)[i] = packbf(h0, h1);
    ((uint32_t*)g_xl)[i] = packbf(l0, l1);
}

__global__ void split_w_kernel(const float* __restrict__ wq,
                               const float* __restrict__ wk,
                               const float* __restrict__ wv,
                               const float* __restrict__ wo) {
    int i = blockIdx.x * blockDim.x + threadIdx.x;
    size_t e = 2 * (size_t)i;
    int m = (int)(e >> 20);
    int r = (int)(e & (NW - 1));
    const float* src = (m == 0) ? wq : (m == 1) ? wk : (m == 2) ? wv : wo;
    float2 v = *(const float2*)(src + r);
    __nv_bfloat16 h0, l0, h1, l1;
    sbf(v.x, h0, l0); sbf(v.y, h1, l1);
    ((uint32_t*)g_wh)[((size_t)m * NW + r) >> 1] = packbf(h0, h1);
    ((uint32_t*)g_wl)[((size_t)m * NW + r) >> 1] = packbf(l0, l1);
}

// ---------------- bf16x3 projection GEMM (128x256 CTA tile) ----------------
#define PSTR 40
#define PA_ELEMS (128 * PSTR)
#define PB_ELEMS (256 * PSTR)
#define PSTAGE_ELEMS (2 * PA_ELEMS + 2 * PB_ELEMS)
#define PSTAGE_BYTES (PSTAGE_ELEMS * 2)
#define PROJ_SMEM (3 * PSTAGE_BYTES)              // 184320 bytes

__device__ __forceinline__ void proj_mainloop(const __nv_bfloat16* __restrict__ Agh,
                                              const __nv_bfloat16* __restrict__ Agl,
                                              const __nv_bfloat16* __restrict__ Bgh,
                                              const __nv_bfloat16* __restrict__ Bgl,
                                              float C[4][8][4], __nv_bfloat16* sm) {
    const int tid = threadIdx.x;
    const int wid = tid >> 5, lane = tid & 31;
    const int g = lane >> 2, t = lane & 3;
    const int wm = (wid >> 2) * 64;
    const int wn = (wid & 3) * 64;

    auto load_chunk = [&](int c, int s) {
        __nv_bfloat16* st = sm + s * PSTAGE_ELEMS;
#pragma unroll
        for (int p = 0; p < 2; p++) {
            const __nv_bfloat16* gp = (p == 0) ? Agh : Agl;
            __nv_bfloat16* sp = st + p * PA_ELEMS;
#pragma unroll
            for (int i = 0; i < 2; i++) {
                int idx = tid + 256 * i;
                int row = idx >> 2, q = idx & 3;
                cp16((uint32_t)__cvta_generic_to_shared(sp + row * PSTR + q * 8),
                     gp + (size_t)row * Dsz + c * 32 + q * 8);
            }
        }
#pragma unroll
        for (int p = 0; p < 2; p++) {
            const __nv_bfloat16* gp = (p == 0) ? Bgh : Bgl;
            __nv_bfloat16* sp = st + 2 * PA_ELEMS + p * PB_ELEMS;
#pragma unroll
            for (int i = 0; i < 4; i++) {
                int idx = tid + 256 * i;
                int row = idx >> 2, q = idx & 3;
                cp16((uint32_t)__cvta_generic_to_shared(sp + row * PSTR + q * 8),
                     gp + (size_t)row * Dsz + c * 32 + q * 8);
            }
        }
    };

    const int NCH = Dsz / 32;
    load_chunk(0, 0); cpcommit();
    load_chunk(1, 1); cpcommit();

    for (int c = 0; c < NCH; c++) {
        if (c == NCH - 1) cpwait0(); else cpwait1();
        __syncthreads();
        if (c + 2 < NCH) { load_chunk(c + 2, (c + 2) % 3); cpcommit(); }

        const __nv_bfloat16* st = sm + (c % 3) * PSTAGE_ELEMS;
        const __nv_bfloat16* sAh = st;
        const __nv_bfloat16* sAl = st + PA_ELEMS;
        const __nv_bfloat16* sBh = st + 2 * PA_ELEMS;
        const __nv_bfloat16* sBl = st + 2 * PA_ELEMS + PB_ELEMS;

#pragma unroll
        for (int ks = 0; ks < 2; ks++) {
            const int kb = ks * 16 + 2 * t;
            uint32_t bh[8][2], bl[8][2];
#pragma unroll
            for (int nt = 0; nt < 8; nt++) {
                const __nv_bfloat16* bp = sBh + (wn + nt * 8 + g) * PSTR + kb;
                const __nv_bfloat16* bq = sBl + (wn + nt * 8 + g) * PSTR + kb;
                bh[nt][0] = *(const uint32_t*)bp;
                bh[nt][1] = *(const uint32_t*)(bp + 8);
                bl[nt][0] = *(const uint32_t*)bq;
                bl[nt][1] = *(const uint32_t*)(bq + 8);
            }
#pragma unroll
            for (int mt = 0; mt < 4; mt++) {
                const int ar = wm + mt * 16 + g;
                const __nv_bfloat16* ap = sAh + ar * PSTR + kb;
                const __nv_bfloat16* aq = sAl + ar * PSTR + kb;
                uint32_t ah[4], al[4];
                ah[0] = *(const uint32_t*)ap;
                ah[1] = *(const uint32_t*)(ap + 8 * PSTR);
                ah[2] = *(const uint32_t*)(ap + 8);
                ah[3] = *(const uint32_t*)(ap + 8 * PSTR + 8);
                al[0] = *(const uint32_t*)aq;
                al[1] = *(const uint32_t*)(aq + 8 * PSTR);
                al[2] = *(const uint32_t*)(aq + 8);
                al[3] = *(const uint32_t*)(aq + 8 * PSTR + 8);
#pragma unroll
                for (int nt = 0; nt < 8; nt++) {
                    mma16(C[mt][nt], ah, bh[nt]);
                    mma16(C[mt][nt], al, bh[nt]);
                    mma16(C[mt][nt], ah, bl[nt]);
                }
            }
        }
    }
}

// ---------------- QKV projection with fused RoPE + Q scale -----------------
__global__ void __launch_bounds__(256, 1) qkv_bf16_kernel(const float* __restrict__ cosp,
                                                          const float* __restrict__ sinp) {
    extern __shared__ __nv_bfloat16 smb[];
    const int z = blockIdx.z;
    const int rowBase = blockIdx.y * 128;
    const int colBase = blockIdx.x * 256;
    __nv_bfloat16* dsth = (z == 0) ? g_qh : (z == 1) ? g_kh : g_vh;
    __nv_bfloat16* dstl = (z == 0) ? g_ql : (z == 1) ? g_kl : g_vl;

    float C[4][8][4];
#pragma unroll
    for (int a = 0; a < 4; a++)
#pragma unroll
        for (int b = 0; b < 8; b++)
#pragma unroll
            for (int c = 0; c < 4; c++) C[a][b][c] = 0.f;

    proj_mainloop(g_xh + (size_t)rowBase * Dsz, g_xl + (size_t)rowBase * Dsz,
                  g_wh + (size_t)z * NW + (size_t)colBase * Dsz,
                  g_wl + (size_t)z * NW + (size_t)colBase * Dsz, C, smb);

    const int tid = threadIdx.x;
    const int wid = tid >> 5, lane = tid & 31;
    const int g = lane >> 2, t = lane & 3;
    const int wm = (wid >> 2) * 64, wn = (wid & 3) * 64;

    // ---- fused RoPE for q (z=0) and k (z=1); pairs (d, d+32) are in
    //      C[mt][nt] / C[mt][nt+4] of the same thread ----
    if (z <= 1) {
#pragma unroll
        for (int mt = 0; mt < 4; mt++) {
            int r = rowBase + wm + mt * 16 + g;
            int l0 = r & (Lsz - 1);
#pragma unroll
            for (int nt = 0; nt < 4; nt++) {
                int d = nt * 8 + 2 * t;        // 0..30
#pragma unroll
                for (int e = 0; e < 4; e++) {
                    int dd = d + (e & 1);
                    int ll = (e < 2) ? l0 : (l0 + 8);
                    float c1 = cosp[ll * HDsz + dd];
                    float s1 = sinp[ll * HDsz + dd];
                    float c2 = cosp[ll * HDsz + dd + 32];
                    float s2 = sinp[ll * HDsz + dd + 32];
                    float x1 = C[mt][nt][e], x2 = C[mt][nt + 4][e];
                    C[mt][nt][e]     = x1 * c1 - x2 * s1;
                    C[mt][nt + 4][e] = x2 * c2 + x1 * s2;
                }
            }
        }
    }
    if (z == 0) {   // fold 1/sqrt(hd) into q (exact power of two)
#pragma unroll
        for (int mt = 0; mt < 4; mt++)
#pragma unroll
            for (int nt = 0; nt < 8; nt++)
#pragma unroll
                for (int e = 0; e < 4; e++) C[mt][nt][e] *= 0.125f;
    }

#pragma unroll
    for (int mt = 0; mt < 4; mt++) {
#pragma unroll
        for (int nt = 0; nt < 8; nt++) {
            int r = rowBase + wm + mt * 16 + g;
            int n = colBase + wn + nt * 8 + 2 * t;
            int h = n >> 6, d = n & 63;
            int b = r >> 11, l = r & 2047;
            size_t o0 = (((size_t)(b * Hsz + h) * Lsz + l) * HDsz + d);
            size_t o1 = (((size_t)(b * Hsz + h) * Lsz + (l + 8)) * HDsz + d);
            __nv_bfloat16 h0, l0, h1, l1;
            sbf(C[mt][nt][0], h0, l0); sbf(C[mt][nt][1], h1, l1);
            *(uint32_t*)(dsth + o0) = packbf(h0, h1);
            *(uint32_t*)(dstl + o0) = packbf(l0, l1);
            sbf(C[mt][nt][2], h0, l0); sbf(C[mt][nt][3], h1, l1);
            *(uint32_t*)(dsth + o1) = packbf(h0, h1);
            *(uint32_t*)(dstl + o1) = packbf(l0, l1);
        }
    }
}

// ---------------- Output projection (writes fp32 out) ----------------------
__global__ void __launch_bounds__(256, 1) oproj_bf16_kernel(float* __restrict__ out) {
    extern __shared__ __nv_bfloat16 smb[];
    const int rowBase = blockIdx.y * 128;
    const int colBase = blockIdx.x * 256;

    float C[4][8][4];
#pragma unroll
    for (int a = 0; a < 4; a++)
#pragma unroll
        for (int b = 0; b < 8; b++)
#pragma unroll
            for (int c = 0; c < 4; c++) C[a][b][c] = 0.f;

    proj_mainloop(g_aoh + (size_t)rowBase * Dsz, g_aol + (size_t)rowBase * Dsz,
                  g_wh + (size_t)3 * NW + (size_t)colBase * Dsz,
                  g_wl + (size_t)3 * NW + (size_t)colBase * Dsz, C, smb);

    const int tid = threadIdx.x;
    const int wid = tid >> 5, lane = tid & 31;
    const int g = lane >> 2, t = lane & 3;
    const int wm = (wid >> 2) * 64, wn = (wid & 3) * 64;
#pragma unroll
    for (int mt = 0; mt < 4; mt++) {
#pragma unroll
        for (int nt = 0; nt < 8; nt++) {
            int r = rowBase + wm + mt * 16 + g;
            int n = colBase + wn + nt * 8 + 2 * t;
            *(float2*)(out + (size_t)r * Dsz + n) = make_float2(C[mt][nt][0], C[mt][nt][1]);
            *(float2*)(out + (size_t)(r + 8) * Dsz + n) = make_float2(C[mt][nt][2], C[mt][nt][3]);
        }
    }
}

// ---------------- Flash attention: register P + cp.async K/V pipeline ------
#define FSTRB 72
#define OFF_QH 0
#define OFF_QL (128 * FSTRB)
#define OFF_KV0 (2 * 128 * FSTRB)
#define KV_PLANE (64 * FSTRB)
#define KV_STAGE (4 * KV_PLANE)
#define FLASH_ELEMS (OFF_KV0 + 2 * KV_STAGE)
#define FLASH_SMEM (FLASH_ELEMS * 2)             // 110592 bytes

__global__ void __launch_bounds__(256, 2) flashmma_kernel() {
    extern __shared__ __nv_bfloat16 smb[];
    __nv_bfloat16* Qh = smb + OFF_QH;
    __nv_bfloat16* Ql = smb + OFF_QL;

    const int tid = threadIdx.x;
    const int wid = tid >> 5, lane = tid & 31;
    const int g = lane >> 2, t = lane & 3;
    const int bh = blockIdx.y;
    const int qt = gridDim.x - 1 - blockIdx.x;
    const int q0 = qt * 128;
    const size_t base = (size_t)bh * Lsz * HDsz;
    const int vln = lane & 15;

    // ---- Q tile: plain copy (already RoPE'd and scaled) ----
#pragma unroll
    for (int i = 0; i < 4; i++) {
        int idx = tid + 256 * i;
        int row = idx >> 3;
        int c8 = (idx & 7) * 8;
        size_t go = base + (size_t)(q0 + row) * HDsz + c8;
        *(float4*)(Qh + row * FSTRB + c8) = *(const float4*)(g_qh + go);
        *(float4*)(Ql + row * FSTRB + c8) = *(const float4*)(g_ql + go);
    }

    auto loadKV = [&](int kt2, int s) {
        __nv_bfloat16* st = smb + OFF_KV0 + s * KV_STAGE;
        const int j0 = kt2 * 64;
#pragma unroll
        for (int p = 0; p < 4; p++) {
            const __nv_bfloat16* gp = (p == 0) ? g_kh : (p == 1) ? g_kl
                                   : (p == 2) ? g_vh : g_vl;
#pragma unroll
            for (int i = 0; i < 2; i++) {
                int idx = tid + 256 * i;
                int row = idx >> 3;
                int c8 = (idx & 7) * 8;
                cp16((uint32_t)__cvta_generic_to_shared(st + p * KV_PLANE + row * FSTRB + c8),
                     gp + base + (size_t)(j0 + row) * HDsz + c8);
            }
        }
    };

    float O[8][4];
#pragma unroll
    for (int i = 0; i < 8; i++)
#pragma unroll
        for (int j = 0; j < 4; j++) O[i][j] = 0.f;
    float mr[2] = {-1e30f, -1e30f};
    float lr[2] = {0.f, 0.f};

    const int pr = wid * 16 + g;
    const int nkt = 2 * qt + 2;

    loadKV(0, 0); cpcommit();

    for (int kt = 0; kt < nkt; kt++) {
        const int s = kt & 1;
        const int j0 = kt * 64;
        __syncthreads();                        // stage s^1 free; Q visible (kt=0)
        if (kt + 1 < nkt) { loadKV(kt + 1, s ^ 1); cpcommit(); cpwait1(); }
        else              { cpwait0(); }
        __syncthreads();                        // stage s ready for all threads

        const __nv_bfloat16* Kh = smb + OFF_KV0 + s * KV_STAGE;
        const __nv_bfloat16* Kl = Kh + KV_PLANE;
        const __nv_bfloat16* Vh = Kl + KV_PLANE;
        const __nv_bfloat16* Vl = Vh + KV_PLANE;
        const uint32_t vh_u32 = (uint32_t)__cvta_generic_to_shared(Vh);
        const uint32_t vl_u32 = (uint32_t)__cvta_generic_to_shared(Vl);

        // ---- GEMM1: S = Q @ K^T (bf16x3) ----
        float S[8][4];
#pragma unroll
        for (int i = 0; i < 8; i++)
#pragma unroll
            for (int j = 0; j < 4; j++) S[i][j] = 0.f;

#pragma unroll
        for (int ks = 0; ks < 4; ks++) {
            const int kb = ks * 16 + 2 * t;
            const __nv_bfloat16* ap = Qh + pr * FSTRB + kb;
            const __nv_bfloat16* aq = Ql + pr * FSTRB + kb;
            uint32_t ah[4], al[4];
            ah[0] = *(const uint32_t*)ap;
            ah[1] = *(const uint32_t*)(ap + 8 * FSTRB);
            ah[2] = *(const uint32_t*)(ap + 8);
            ah[3] = *(const uint32_t*)(ap + 8 * FSTRB + 8);
            al[0] = *(const uint32_t*)aq;
            al[1] = *(const uint32_t*)(aq + 8 * FSTRB);
            al[2] = *(const uint32_t*)(aq + 8);
            al[3] = *(const uint32_t*)(aq + 8 * FSTRB + 8);
#pragma unroll
            for (int nt = 0; nt < 8; nt++) {
                const __nv_bfloat16* kp = Kh + (nt * 8 + g) * FSTRB + kb;
                const __nv_bfloat16* kq = Kl + (nt * 8 + g) * FSTRB + kb;
                uint32_t bh2[2] = {*(const uint32_t*)kp, *(const uint32_t*)(kp + 8)};
                uint32_t bl2[2] = {*(const uint32_t*)kq, *(const uint32_t*)(kq + 8)};
                mma16(S[nt], ah, bh2);
                mma16(S[nt], al, bh2);
                mma16(S[nt], ah, bl2);
            }
        }

        // ---- causal mask (diagonal tiles only) ----
        if (kt >= 2 * qt) {
            int r0g = q0 + pr;
#pragma unroll
            for (int nt = 0; nt < 8; nt++) {
                int c0 = j0 + nt * 8 + 2 * t;
                if (c0 > r0g)         S[nt][0] = -1e30f;
                if (c0 + 1 > r0g)     S[nt][1] = -1e30f;
                if (c0 > r0g + 8)     S[nt][2] = -1e30f;
                if (c0 + 1 > r0g + 8) S[nt][3] = -1e30f;
            }
        }

        // ---- online softmax ----
#pragma unroll
        for (int h2 = 0; h2 < 2; h2++) {
            float mloc = -1e30f;
#pragma unroll
            for (int nt = 0; nt < 8; nt++)
                mloc = fmaxf(mloc, fmaxf(S[nt][2 * h2], S[nt][2 * h2 + 1]));
            mloc = fmaxf(mloc, __shfl_xor_sync(0xffffffffu, mloc, 1));
            mloc = fmaxf(mloc, __shfl_xor_sync(0xffffffffu, mloc, 2));
            float mnew = fmaxf(mr[h2], mloc);
            float sc = __expf(mr[h2] - mnew);
            float ls = 0.f;
#pragma unroll
            for (int nt = 0; nt < 8; nt++) {
                float p0 = __expf(S[nt][2 * h2] - mnew);
                float p1 = __expf(S[nt][2 * h2 + 1] - mnew);
                S[nt][2 * h2] = p0; S[nt][2 * h2 + 1] = p1;
                ls += p0 + p1;
            }
            ls += __shfl_xor_sync(0xffffffffu, ls, 1);
            ls += __shfl_xor_sync(0xffffffffu, ls, 2);
            lr[h2] = lr[h2] * sc + ls;
            mr[h2] = mnew;
#pragma unroll
            for (int nt = 0; nt < 8; nt++) {
                O[nt][2 * h2] *= sc;
                O[nt][2 * h2 + 1] *= sc;
            }
        }

        // ---- GEMM2: O += P @ V.  P's A-fragments come straight from S's
        //      C-fragments (identical thread-layout) — no smem round trip ----
#pragma unroll
        for (int ks = 0; ks < 4; ks++) {
            uint32_t ah[4], al[4];
            {
                __nv_bfloat16 h0, l0, h1, l1;
                sbf(S[2 * ks][0], h0, l0);     sbf(S[2 * ks][1], h1, l1);
                ah[0] = packbf(h0, h1);        al[0] = packbf(l0, l1);
                sbf(S[2 * ks][2], h0, l0);     sbf(S[2 * ks][3], h1, l1);
                ah[1] = packbf(h0, h1);        al[1] = packbf(l0, l1);
                sbf(S[2 * ks + 1][0], h0, l0); sbf(S[2 * ks + 1][1], h1, l1);
                ah[2] = packbf(h0, h1);        al[2] = packbf(l0, l1);
                sbf(S[2 * ks + 1][2], h0, l0); sbf(S[2 * ks + 1][3], h1, l1);
                ah[3] = packbf(h0, h1);        al[3] = packbf(l0, l1);
            }
            const uint32_t rowoff = ((ks * 16 + vln) * FSTRB) * 2;
#pragma unroll
            for (int dt = 0; dt < 8; dt++) {
                uint32_t bh2[2], bl2[2];
                ldsm_x2_trans(bh2[0], bh2[1], vh_u32 + rowoff + dt * 16);
                ldsm_x2_trans(bl2[0], bl2[1], vl_u32 + rowoff + dt * 16);
                mma16(O[dt], ah, bh2);
                mma16(O[dt], al, bh2);
                mma16(O[dt], ah, bl2);
            }
        }
    }

    // ---- epilogue: normalize, split, write ao planes ----
    const float i0 = 1.f / lr[0];
    const float i1 = 1.f / lr[1];
    const int r = q0 + pr;
    const int b = bh >> 4;
    const int h = bh & 15;
    const size_t ob = (size_t)b * Lsz * Dsz + (size_t)h * HDsz;
#pragma unroll
    for (int dt = 0; dt < 8; dt++) {
        int d = dt * 8 + 2 * t;
        __nv_bfloat16 h0, l0, h1, l1;
        sbf(O[dt][0] * i0, h0, l0); sbf(O[dt][1] * i0, h1, l1);
        *(uint32_t*)(g_aoh + ob + (size_t)r * Dsz + d) = packbf(h0, h1);
        *(uint32_t*)(g_aol + ob + (size_t)r * Dsz + d) = packbf(l0, l1);
        sbf(O[dt][2] * i1, h0, l0); sbf(O[dt][3] * i1, h1, l1);
        *(uint32_t*)(g_aoh + ob + (size_t)(r + 8) * Dsz + d) = packbf(h0, h1);
        *(uint32_t*)(g_aol + ob + (size_t)(r + 8) * Dsz + d) = packbf(l0, l1);
    }
}

// ---------------------------------------------------------------------------
extern "C" void kernel_launch(void* const* d_in, const int* in_sizes, int n_in,
                              void* d_out, int out_size) {
    (void)in_sizes; (void)n_in; (void)out_size;
    const float* x    = (const float*)d_in[0];
    const float* cosp = (const float*)d_in[1];
    const float* sinp = (const float*)d_in[2];
    const float* wq   = (const float*)d_in[3];
    const float* wk   = (const float*)d_in[4];
    const float* wv   = (const float*)d_in[5];
    const float* wo   = (const float*)d_in[6];
    float* out = (float*)d_out;

    cudaFuncSetAttribute(qkv_bf16_kernel,
                         cudaFuncAttributeMaxDynamicSharedMemorySize, PROJ_SMEM);
    cudaFuncSetAttribute(oproj_bf16_kernel,
                         cudaFuncAttributeMaxDynamicSharedMemorySize, PROJ_SMEM);
    cudaFuncSetAttribute(flashmma_kernel,
                         cudaFuncAttributeMaxDynamicSharedMemorySize, FLASH_SMEM);

    // 1) split inputs into bf16 hi/lo planes
    split_x_kernel<<<(NX / 2) / 256, 256>>>(x);
    split_w_kernel<<<(4 * NW / 2) / 256, 256>>>(wq, wk, wv, wo);

    // 2) QKV projections with fused RoPE + q-scale -> q/k/v planes
    qkv_bf16_kernel<<<dim3(Dsz / 256, (Bsz * Lsz) / 128, 3), 256, PROJ_SMEM>>>(cosp, sinp);

    // 3) causal flash attention -> ao planes
    flashmma_kernel<<<dim3(Lsz / 128, Bsz * Hsz), 256, FLASH_SMEM>>>();

    // 4) output projection -> d_out
    oproj_bf16_kernel<<<dim3(Dsz / 256, (Bsz * Lsz) / 128), 256, PROJ_SMEM>>>(out);
}

// round 9
// speedup vs baseline: 3.4683x; 1.0769x over previous
#include <cuda_runtime.h>
#include <cuda_bf16.h>
#include <math.h>
#include <stdint.h>

// Problem constants: B=2, L=2048, D=1024, H=16, hd=64
#define Bsz 2
#define Lsz 2048
#define Dsz 1024
#define Hsz 16
#define HDsz 64

#define NQKV (Bsz * Hsz * Lsz * HDsz)   // 4194304
#define NX   (Bsz * Lsz * Dsz)          // 4194304
#define NW   (Dsz * Dsz)                // 1048576 = 2^20

#define NQT (Lsz / 128)                 // 16 q-tiles
#define NITEMS (NQT * Bsz * Hsz)        // 512 work items
#define FLASH_CTAS 296                  // 2 per SM x 148 SMs

// ---------------- device scratch: bf16 hi/lo planes ------------------------
__device__ __nv_bfloat16 g_xh[NX],  g_xl[NX];
__device__ __nv_bfloat16 g_wh[4 * NW], g_wl[4 * NW];
__device__ __nv_bfloat16 g_qh[NQKV], g_ql[NQKV];
__device__ __nv_bfloat16 g_kh[NQKV], g_kl[NQKV];
__device__ __nv_bfloat16 g_vh[NQKV], g_vl[NQKV];
__device__ __nv_bfloat16 g_aoh[NX], g_aol[NX];
__device__ int g_wctr;                  // flash work-queue counter

// ---------------- helpers --------------------------------------------------
__device__ __forceinline__ void sbf(float x, __nv_bfloat16& h, __nv_bfloat16& l) {
    h = __float2bfloat16(x);
    l = __float2bfloat16(x - __bfloat162float(h));
}
__device__ __forceinline__ uint32_t packbf(__nv_bfloat16 a, __nv_bfloat16 b) {
    uint16_t au = *(uint16_t*)&a, bu = *(uint16_t*)&b;
    return (uint32_t)au | ((uint32_t)bu << 16);
}

__device__ __forceinline__ void mma16(float c[4], const uint32_t a[4], const uint32_t b[2]) {
    asm volatile(
        "mma.sync.aligned.m16n8k16.row.col.f32.bf16.bf16.f32 "
        "{%0,%1,%2,%3}, {%4,%5,%6,%7}, {%8,%9}, {%0,%1,%2,%3};\n"
        : "+f"(c[0]), "+f"(c[1]), "+f"(c[2]), "+f"(c[3])
        : "r"(a[0]), "r"(a[1]), "r"(a[2]), "r"(a[3]), "r"(b[0]), "r"(b[1]));
}

__device__ __forceinline__ void ldsm_x2_trans(uint32_t& r0, uint32_t& r1, uint32_t addr) {
    asm volatile("ldmatrix.sync.aligned.m8n8.x2.trans.shared.b16 {%0,%1}, [%2];"
                 : "=r"(r0), "=r"(r1) : "r"(addr));
}

__device__ __forceinline__ void cp16(uint32_t dst, const void* src) {
    asm volatile("cp.async.cg.shared.global [%0],[%1],16;\n" ::"r"(dst), "l"(src) : "memory");
}
__device__ __forceinline__ void cpcommit() { asm volatile("cp.async.commit_group;\n" ::: "memory"); }
__device__ __forceinline__ void cpwait1()  { asm volatile("cp.async.wait_group 1;\n" ::: "memory"); }
__device__ __forceinline__ void cpwait0()  { asm volatile("cp.async.wait_group 0;\n" ::: "memory"); }

// ---------------- split kernels: fp32 -> bf16 hi/lo planes -----------------
__global__ void split_x_kernel(const float* __restrict__ in) {
    int i = blockIdx.x * blockDim.x + threadIdx.x;
    if (i == 0) g_wctr = 0;             // reset flash work queue every launch
    float2 v = *(const float2*)(in + 2 * (size_t)i);
    __nv_bfloat16 h0, l0, h1, l1;
    sbf(v.x, h0, l0); sbf(v.y, h1, l1);
    ((uint32_t*)g_xh)[i] = packbf(h0, h1);
    ((uint32_t*)g_xl)[i] = packbf(l0, l1);
}

__global__ void split_w_kernel(const float* __restrict__ wq,
                               const float* __restrict__ wk,
                               const float* __restrict__ wv,
                               const float* __restrict__ wo) {
    int i = blockIdx.x * blockDim.x + threadIdx.x;
    size_t e = 2 * (size_t)i;
    int m = (int)(e >> 20);
    int r = (int)(e & (NW - 1));
    const float* src = (m == 0) ? wq : (m == 1) ? wk : (m == 2) ? wv : wo;
    float2 v = *(const float2*)(src + r);
    __nv_bfloat16 h0, l0, h1, l1;
    sbf(v.x, h0, l0); sbf(v.y, h1, l1);
    ((uint32_t*)g_wh)[((size_t)m * NW + r) >> 1] = packbf(h0, h1);
    ((uint32_t*)g_wl)[((size_t)m * NW + r) >> 1] = packbf(l0, l1);
}

// ---------------- bf16x3 projection GEMM (128x256 CTA tile) ----------------
#define PSTR 40
#define PA_ELEMS (128 * PSTR)
#define PB_ELEMS (256 * PSTR)
#define PSTAGE_ELEMS (2 * PA_ELEMS + 2 * PB_ELEMS)
#define PSTAGE_BYTES (PSTAGE_ELEMS * 2)
#define PROJ_SMEM (3 * PSTAGE_BYTES)              // 184320 bytes

__device__ __forceinline__ void proj_mainloop(const __nv_bfloat16* __restrict__ Agh,
                                              const __nv_bfloat16* __restrict__ Agl,
                                              const __nv_bfloat16* __restrict__ Bgh,
                                              const __nv_bfloat16* __restrict__ Bgl,
                                              float C[4][8][4], __nv_bfloat16* sm) {
    const int tid = threadIdx.x;
    const int wid = tid >> 5, lane = tid & 31;
    const int g = lane >> 2, t = lane & 3;
    const int wm = (wid >> 2) * 64;
    const int wn = (wid & 3) * 64;

    auto load_chunk = [&](int c, int s) {
        __nv_bfloat16* st = sm + s * PSTAGE_ELEMS;
#pragma unroll
        for (int p = 0; p < 2; p++) {
            const __nv_bfloat16* gp = (p == 0) ? Agh : Agl;
            __nv_bfloat16* sp = st + p * PA_ELEMS;
#pragma unroll
            for (int i = 0; i < 2; i++) {
                int idx = tid + 256 * i;
                int row = idx >> 2, q = idx & 3;
                cp16((uint32_t)__cvta_generic_to_shared(sp + row * PSTR + q * 8),
                     gp + (size_t)row * Dsz + c * 32 + q * 8);
            }
        }
#pragma unroll
        for (int p = 0; p < 2; p++) {
            const __nv_bfloat16* gp = (p == 0) ? Bgh : Bgl;
            __nv_bfloat16* sp = st + 2 * PA_ELEMS + p * PB_ELEMS;
#pragma unroll
            for (int i = 0; i < 4; i++) {
                int idx = tid + 256 * i;
                int row = idx >> 2, q = idx & 3;
                cp16((uint32_t)__cvta_generic_to_shared(sp + row * PSTR + q * 8),
                     gp + (size_t)row * Dsz + c * 32 + q * 8);
            }
        }
    };

    const int NCH = Dsz / 32;
    load_chunk(0, 0); cpcommit();
    load_chunk(1, 1); cpcommit();

    for (int c = 0; c < NCH; c++) {
        if (c == NCH - 1) cpwait0(); else cpwait1();
        __syncthreads();
        if (c + 2 < NCH) { load_chunk(c + 2, (c + 2) % 3); cpcommit(); }

        const __nv_bfloat16* st = sm + (c % 3) * PSTAGE_ELEMS;
        const __nv_bfloat16* sAh = st;
        const __nv_bfloat16* sAl = st + PA_ELEMS;
        const __nv_bfloat16* sBh = st + 2 * PA_ELEMS;
        const __nv_bfloat16* sBl = st + 2 * PA_ELEMS + PB_ELEMS;

#pragma unroll
        for (int ks = 0; ks < 2; ks++) {
            const int kb = ks * 16 + 2 * t;
            uint32_t bh[8][2], bl[8][2];
#pragma unroll
            for (int nt = 0; nt < 8; nt++) {
                const __nv_bfloat16* bp = sBh + (wn + nt * 8 + g) * PSTR + kb;
                const __nv_bfloat16* bq = sBl + (wn + nt * 8 + g) * PSTR + kb;
                bh[nt][0] = *(const uint32_t*)bp;
                bh[nt][1] = *(const uint32_t*)(bp + 8);
                bl[nt][0] = *(const uint32_t*)bq;
                bl[nt][1] = *(const uint32_t*)(bq + 8);
            }
#pragma unroll
            for (int mt = 0; mt < 4; mt++) {
                const int ar = wm + mt * 16 + g;
                const __nv_bfloat16* ap = sAh + ar * PSTR + kb;
                const __nv_bfloat16* aq = sAl + ar * PSTR + kb;
                uint32_t ah[4], al[4];
                ah[0] = *(const uint32_t*)ap;
                ah[1] = *(const uint32_t*)(ap + 8 * PSTR);
                ah[2] = *(const uint32_t*)(ap + 8);
                ah[3] = *(const uint32_t*)(ap + 8 * PSTR + 8);
                al[0] = *(const uint32_t*)aq;
                al[1] = *(const uint32_t*)(aq + 8 * PSTR);
                al[2] = *(const uint32_t*)(aq + 8);
                al[3] = *(const uint32_t*)(aq + 8 * PSTR + 8);
#pragma unroll
                for (int nt = 0; nt < 8; nt++) {
                    mma16(C[mt][nt], ah, bh[nt]);
                    mma16(C[mt][nt], al, bh[nt]);
                    mma16(C[mt][nt], ah, bl[nt]);
                }
            }
        }
    }
}

// ---------------- QKV projection with fused RoPE + Q scale -----------------
__global__ void __launch_bounds__(256, 1) qkv_bf16_kernel(const float* __restrict__ cosp,
                                                          const float* __restrict__ sinp) {
    extern __shared__ __nv_bfloat16 smb[];
    const int z = blockIdx.z;
    const int rowBase = blockIdx.y * 128;
    const int colBase = blockIdx.x * 256;
    __nv_bfloat16* dsth = (z == 0) ? g_qh : (z == 1) ? g_kh : g_vh;
    __nv_bfloat16* dstl = (z == 0) ? g_ql : (z == 1) ? g_kl : g_vl;

    float C[4][8][4];
#pragma unroll
    for (int a = 0; a < 4; a++)
#pragma unroll
        for (int b = 0; b < 8; b++)
#pragma unroll
            for (int c = 0; c < 4; c++) C[a][b][c] = 0.f;

    proj_mainloop(g_xh + (size_t)rowBase * Dsz, g_xl + (size_t)rowBase * Dsz,
                  g_wh + (size_t)z * NW + (size_t)colBase * Dsz,
                  g_wl + (size_t)z * NW + (size_t)colBase * Dsz, C, smb);

    const int tid = threadIdx.x;
    const int wid = tid >> 5, lane = tid & 31;
    const int g = lane >> 2, t = lane & 3;
    const int wm = (wid >> 2) * 64, wn = (wid & 3) * 64;

    if (z <= 1) {
#pragma unroll
        for (int mt = 0; mt < 4; mt++) {
            int r = rowBase + wm + mt * 16 + g;
            int l0 = r & (Lsz - 1);
#pragma unroll
            for (int nt = 0; nt < 4; nt++) {
                int d = nt * 8 + 2 * t;
#pragma unroll
                for (int e = 0; e < 4; e++) {
                    int dd = d + (e & 1);
                    int ll = (e < 2) ? l0 : (l0 + 8);
                    float c1 = cosp[ll * HDsz + dd];
                    float s1 = sinp[ll * HDsz + dd];
                    float c2 = cosp[ll * HDsz + dd + 32];
                    float s2 = sinp[ll * HDsz + dd + 32];
                    float x1 = C[mt][nt][e], x2 = C[mt][nt + 4][e];
                    C[mt][nt][e]     = x1 * c1 - x2 * s1;
                    C[mt][nt + 4][e] = x2 * c2 + x1 * s2;
                }
            }
        }
    }
    if (z == 0) {
#pragma unroll
        for (int mt = 0; mt < 4; mt++)
#pragma unroll
            for (int nt = 0; nt < 8; nt++)
#pragma unroll
                for (int e = 0; e < 4; e++) C[mt][nt][e] *= 0.125f;
    }

#pragma unroll
    for (int mt = 0; mt < 4; mt++) {
#pragma unroll
        for (int nt = 0; nt < 8; nt++) {
            int r = rowBase + wm + mt * 16 + g;
            int n = colBase + wn + nt * 8 + 2 * t;
            int h = n >> 6, d = n & 63;
            int b = r >> 11, l = r & 2047;
            size_t o0 = (((size_t)(b * Hsz + h) * Lsz + l) * HDsz + d);
            size_t o1 = (((size_t)(b * Hsz + h) * Lsz + (l + 8)) * HDsz + d);
            __nv_bfloat16 h0, l0, h1, l1;
            sbf(C[mt][nt][0], h0, l0); sbf(C[mt][nt][1], h1, l1);
            *(uint32_t*)(dsth + o0) = packbf(h0, h1);
            *(uint32_t*)(dstl + o0) = packbf(l0, l1);
            sbf(C[mt][nt][2], h0, l0); sbf(C[mt][nt][3], h1, l1);
            *(uint32_t*)(dsth + o1) = packbf(h0, h1);
            *(uint32_t*)(dstl + o1) = packbf(l0, l1);
        }
    }
}

// ---------------- Output projection (writes fp32 out) ----------------------
__global__ void __launch_bounds__(256, 1) oproj_bf16_kernel(float* __restrict__ out) {
    extern __shared__ __nv_bfloat16 smb[];
    const int rowBase = blockIdx.y * 128;
    const int colBase = blockIdx.x * 256;

    float C[4][8][4];
#pragma unroll
    for (int a = 0; a < 4; a++)
#pragma unroll
        for (int b = 0; b < 8; b++)
#pragma unroll
            for (int c = 0; c < 4; c++) C[a][b][c] = 0.f;

    proj_mainloop(g_aoh + (size_t)rowBase * Dsz, g_aol + (size_t)rowBase * Dsz,
                  g_wh + (size_t)3 * NW + (size_t)colBase * Dsz,
                  g_wl + (size_t)3 * NW + (size_t)colBase * Dsz, C, smb);

    const int tid = threadIdx.x;
    const int wid = tid >> 5, lane = tid & 31;
    const int g = lane >> 2, t = lane & 3;
    const int wm = (wid >> 2) * 64, wn = (wid & 3) * 64;
#pragma unroll
    for (int mt = 0; mt < 4; mt++) {
#pragma unroll
        for (int nt = 0; nt < 8; nt++) {
            int r = rowBase + wm + mt * 16 + g;
            int n = colBase + wn + nt * 8 + 2 * t;
            *(float2*)(out + (size_t)r * Dsz + n) = make_float2(C[mt][nt][0], C[mt][nt][1]);
            *(float2*)(out + (size_t)(r + 8) * Dsz + n) = make_float2(C[mt][nt][2], C[mt][nt][3]);
        }
    }
}

// ---------------- Flash attention: persistent CTAs + work queue ------------
#define FSTRB 72
#define OFF_QH 0
#define OFF_QL (128 * FSTRB)
#define OFF_KV0 (2 * 128 * FSTRB)
#define KV_PLANE (64 * FSTRB)
#define KV_STAGE (4 * KV_PLANE)
#define FLASH_ELEMS (OFF_KV0 + 2 * KV_STAGE)
#define FLASH_SMEM (FLASH_ELEMS * 2 + 16)        // +16 for s_item slot

__global__ void __launch_bounds__(256, 2) flashmma_kernel() {
    extern __shared__ __nv_bfloat16 smb[];
    __nv_bfloat16* Qh = smb + OFF_QH;
    __nv_bfloat16* Ql = smb + OFF_QL;
    int* s_item = (int*)(smb + FLASH_ELEMS);

    const int tid = threadIdx.x;
    const int wid = tid >> 5, lane = tid & 31;
    const int g = lane >> 2, t = lane & 3;
    const int vln = lane & 15;
    const int pr = wid * 16 + g;

    for (;;) {
        __syncthreads();                         // prev item done with smem/s_item
        if (tid == 0) *s_item = atomicAdd(&g_wctr, 1);
        __syncthreads();
        const int item = *s_item;
        if (item >= NITEMS) break;

        // biggest-first: item 0..31 -> qt=15 (34 iters), ..., 480..511 -> qt=0
        const int qt = NQT - 1 - (item >> 5);
        const int bh = item & 31;
        const int q0 = qt * 128;
        const size_t base = (size_t)bh * Lsz * HDsz;

        // ---- Q tile ----
#pragma unroll
        for (int i = 0; i < 4; i++) {
            int idx = tid + 256 * i;
            int row = idx >> 3;
            int c8 = (idx & 7) * 8;
            size_t go = base + (size_t)(q0 + row) * HDsz + c8;
            *(float4*)(Qh + row * FSTRB + c8) = *(const float4*)(g_qh + go);
            *(float4*)(Ql + row * FSTRB + c8) = *(const float4*)(g_ql + go);
        }

        auto loadKV = [&](int kt2, int s) {
            __nv_bfloat16* st = smb + OFF_KV0 + s * KV_STAGE;
            const int j0 = kt2 * 64;
#pragma unroll
            for (int p = 0; p < 4; p++) {
                const __nv_bfloat16* gp = (p == 0) ? g_kh : (p == 1) ? g_kl
                                       : (p == 2) ? g_vh : g_vl;
#pragma unroll
                for (int i = 0; i < 2; i++) {
                    int idx = tid + 256 * i;
                    int row = idx >> 3;
                    int c8 = (idx & 7) * 8;
                    cp16((uint32_t)__cvta_generic_to_shared(st + p * KV_PLANE + row * FSTRB + c8),
                         gp + base + (size_t)(j0 + row) * HDsz + c8);
                }
            }
        };

        float O[8][4];
#pragma unroll
        for (int i = 0; i < 8; i++)
#pragma unroll
            for (int j = 0; j < 4; j++) O[i][j] = 0.f;
        float mr[2] = {-1e30f, -1e30f};
        float lr[2] = {0.f, 0.f};

        const int nkt = 2 * qt + 2;
        loadKV(0, 0); cpcommit();

        for (int kt = 0; kt < nkt; kt++) {
            const int s = kt & 1;
            const int j0 = kt * 64;
            __syncthreads();
            if (kt + 1 < nkt) { loadKV(kt + 1, s ^ 1); cpcommit(); cpwait1(); }
            else              { cpwait0(); }
            __syncthreads();

            const __nv_bfloat16* Kh = smb + OFF_KV0 + s * KV_STAGE;
            const __nv_bfloat16* Kl = Kh + KV_PLANE;
            const __nv_bfloat16* Vh = Kl + KV_PLANE;
            const __nv_bfloat16* Vl = Vh + KV_PLANE;
            const uint32_t vh_u32 = (uint32_t)__cvta_generic_to_shared(Vh);
            const uint32_t vl_u32 = (uint32_t)__cvta_generic_to_shared(Vl);

            float S[8][4];
#pragma unroll
            for (int i = 0; i < 8; i++)
#pragma unroll
                for (int j = 0; j < 4; j++) S[i][j] = 0.f;

#pragma unroll
            for (int ks = 0; ks < 4; ks++) {
                const int kb = ks * 16 + 2 * t;
                const __nv_bfloat16* ap = Qh + pr * FSTRB + kb;
                const __nv_bfloat16* aq = Ql + pr * FSTRB + kb;
                uint32_t ah[4], al[4];
                ah[0] = *(const uint32_t*)ap;
                ah[1] = *(const uint32_t*)(ap + 8 * FSTRB);
                ah[2] = *(const uint32_t*)(ap + 8);
                ah[3] = *(const uint32_t*)(ap + 8 * FSTRB + 8);
                al[0] = *(const uint32_t*)aq;
                al[1] = *(const uint32_t*)(aq + 8 * FSTRB);
                al[2] = *(const uint32_t*)(aq + 8);
                al[3] = *(const uint32_t*)(aq + 8 * FSTRB + 8);
#pragma unroll
                for (int nt = 0; nt < 8; nt++) {
                    const __nv_bfloat16* kp = Kh + (nt * 8 + g) * FSTRB + kb;
                    const __nv_bfloat16* kq = Kl + (nt * 8 + g) * FSTRB + kb;
                    uint32_t bh2[2] = {*(const uint32_t*)kp, *(const uint32_t*)(kp + 8)};
                    uint32_t bl2[2] = {*(const uint32_t*)kq, *(const uint32_t*)(kq + 8)};
                    mma16(S[nt], ah, bh2);
                    mma16(S[nt], al, bh2);
                    mma16(S[nt], ah, bl2);
                }
            }

            if (kt >= 2 * qt) {
                int r0g = q0 + pr;
#pragma unroll
                for (int nt = 0; nt < 8; nt++) {
                    int c0 = j0 + nt * 8 + 2 * t;
                    if (c0 > r0g)         S[nt][0] = -1e30f;
                    if (c0 + 1 > r0g)     S[nt][1] = -1e30f;
                    if (c0 > r0g + 8)     S[nt][2] = -1e30f;
                    if (c0 + 1 > r0g + 8) S[nt][3] = -1e30f;
                }
            }

#pragma unroll
            for (int h2 = 0; h2 < 2; h2++) {
                float mloc = -1e30f;
#pragma unroll
                for (int nt = 0; nt < 8; nt++)
                    mloc = fmaxf(mloc, fmaxf(S[nt][2 * h2], S[nt][2 * h2 + 1]));
                mloc = fmaxf(mloc, __shfl_xor_sync(0xffffffffu, mloc, 1));
                mloc = fmaxf(mloc, __shfl_xor_sync(0xffffffffu, mloc, 2));
                float mnew = fmaxf(mr[h2], mloc);
                float sc = __expf(mr[h2] - mnew);
                float ls = 0.f;
#pragma unroll
                for (int nt = 0; nt < 8; nt++) {
                    float p0 = __expf(S[nt][2 * h2] - mnew);
                    float p1 = __expf(S[nt][2 * h2 + 1] - mnew);
                    S[nt][2 * h2] = p0; S[nt][2 * h2 + 1] = p1;
                    ls += p0 + p1;
                }
                ls += __shfl_xor_sync(0xffffffffu, ls, 1);
                ls += __shfl_xor_sync(0xffffffffu, ls, 2);
                lr[h2] = lr[h2] * sc + ls;
                mr[h2] = mnew;
#pragma unroll
                for (int nt = 0; nt < 8; nt++) {
                    O[nt][2 * h2] *= sc;
                    O[nt][2 * h2 + 1] *= sc;
                }
            }

#pragma unroll
            for (int ks = 0; ks < 4; ks++) {
                uint32_t ah[4], al[4];
                {
                    __nv_bfloat16 h0, l0, h1, l1;
                    sbf(S[2 * ks][0], h0, l0);     sbf(S[2 * ks][1], h1, l1);
                    ah[0] = packbf(h0, h1);        al[0] = packbf(l0, l1);
                    sbf(S[2 * ks][2], h0, l0);     sbf(S[2 * ks][3], h1, l1);
                    ah[1] = packbf(h0, h1);        al[1] = packbf(l0, l1);
                    sbf(S[2 * ks + 1][0], h0, l0); sbf(S[2 * ks + 1][1], h1, l1);
                    ah[2] = packbf(h0, h1);        al[2] = packbf(l0, l1);
                    sbf(S[2 * ks + 1][2], h0, l0); sbf(S[2 * ks + 1][3], h1, l1);
                    ah[3] = packbf(h0, h1);        al[3] = packbf(l0, l1);
                }
                const uint32_t rowoff = ((ks * 16 + vln) * FSTRB) * 2;
#pragma unroll
                for (int dt = 0; dt < 8; dt++) {
                    uint32_t bh2[2], bl2[2];
                    ldsm_x2_trans(bh2[0], bh2[1], vh_u32 + rowoff + dt * 16);
                    ldsm_x2_trans(bl2[0], bl2[1], vl_u32 + rowoff + dt * 16);
                    mma16(O[dt], ah, bh2);
                    mma16(O[dt], al, bh2);
                    mma16(O[dt], ah, bl2);
                }
            }
        }

        // ---- epilogue ----
        const float i0 = 1.f / lr[0];
        const float i1 = 1.f / lr[1];
        const int r = q0 + pr;
        const int b = bh >> 4;
        const int h = bh & 15;
        const size_t ob = (size_t)b * Lsz * Dsz + (size_t)h * HDsz;
#pragma unroll
        for (int dt = 0; dt < 8; dt++) {
            int d = dt * 8 + 2 * t;
            __nv_bfloat16 h0, l0, h1, l1;
            sbf(O[dt][0] * i0, h0, l0); sbf(O[dt][1] * i0, h1, l1);
            *(uint32_t*)(g_aoh + ob + (size_t)r * Dsz + d) = packbf(h0, h1);
            *(uint32_t*)(g_aol + ob + (size_t)r * Dsz + d) = packbf(l0, l1);
            sbf(O[dt][2] * i1, h0, l0); sbf(O[dt][3] * i1, h1, l1);
            *(uint32_t*)(g_aoh + ob + (size_t)(r + 8) * Dsz + d) = packbf(h0, h1);
            *(uint32_t*)(g_aol + ob + (size_t)(r + 8) * Dsz + d) = packbf(l0, l1);
        }
    }
}

// ---------------------------------------------------------------------------
extern "C" void kernel_launch(void* const* d_in, const int* in_sizes, int n_in,
                              void* d_out, int out_size) {
    (void)in_sizes; (void)n_in; (void)out_size;
    const float* x    = (const float*)d_in[0];
    const float* cosp = (const float*)d_in[1];
    const float* sinp = (const float*)d_in[2];
    const float* wq   = (const float*)d_in[3];
    const float* wk   = (const float*)d_in[4];
    const float* wv   = (const float*)d_in[5];
    const float* wo   = (const float*)d_in[6];
    float* out = (float*)d_out;

    cudaFuncSetAttribute(qkv_bf16_kernel,
                         cudaFuncAttributeMaxDynamicSharedMemorySize, PROJ_SMEM);
    cudaFuncSetAttribute(oproj_bf16_kernel,
                         cudaFuncAttributeMaxDynamicSharedMemorySize, PROJ_SMEM);
    cudaFuncSetAttribute(flashmma_kernel,
                         cudaFuncAttributeMaxDynamicSharedMemorySize, FLASH_SMEM);

    // 1) split inputs into bf16 hi/lo planes (also resets flash work queue)
    split_x_kernel<<<(NX / 2) / 256, 256>>>(x);
    split_w_kernel<<<(4 * NW / 2) / 256, 256>>>(wq, wk, wv, wo);

    // 2) QKV projections with fused RoPE + q-scale -> q/k/v planes
    qkv_bf16_kernel<<<dim3(Dsz / 256, (Bsz * Lsz) / 128, 3), 256, PROJ_SMEM>>>(cosp, sinp);

    // 3) causal flash attention (persistent, work-queue balanced) -> ao planes
    flashmma_kernel<<<FLASH_CTAS, 256, FLASH_SMEM>>>();

    // 4) output projection -> d_out
    oproj_bf16_kernel<<<dim3(Dsz / 256, (Bsz * Lsz) / 128), 256, PROJ_SMEM>>>(out);
}